// round 4
// baseline (speedup 1.0000x reference)
#include <cuda_runtime.h>
#include <cuda_bf16.h>
#include <math.h>
#include <stdint.h>

// Problem constants
#define BB   2
#define SS   2048
#define EE   1024
#define HH   16
#define DD   64
#define HALF 32
#define MROWS 4096            // B*S
#define NQKV  1152            // H*D + D + D
#define EPSF  1.1920929e-07f  // finfo(float32).eps

// ---------------- device scratch (static, allocation-free) ----------------
__device__ float g_Wqkv[1024 * NQKV];   // packed [Wq | Wk | Wv], k-major rows
__device__ float g_qkv[MROWS * NQKV];   // projections, later rope/normed in place
__device__ float g_attn[MROWS * EE];    // attention output (B,S,H*D)

// ---------------- pack Wq|Wk|Wv ----------------
__global__ void pack_kernel(const float* __restrict__ Wq,
                            const float* __restrict__ Wk,
                            const float* __restrict__ Wv,
                            float* __restrict__ Wqkv)
{
    int idx = blockIdx.x * blockDim.x + threadIdx.x;
    if (idx >= 1024 * NQKV) return;
    int k = idx / NQKV;
    int n = idx - k * NQKV;
    float v;
    if (n < 1024)       v = Wq[k * 1024 + n];
    else if (n < 1088)  v = Wk[k * 64 + (n - 1024)];
    else                v = Wv[k * 64 + (n - 1088)];
    Wqkv[idx] = v;
}

// ---------------- generic 128x128x8 SGEMM, 8x8 micro-tiles ----------------
// C[M,N] = A[M,K] @ B[K,N]; M%128==0, N%128==0, K%8==0 (true for all our uses)
__global__ __launch_bounds__(256, 2)
void sgemm128(const float* __restrict__ A, const float* __restrict__ B,
              float* __restrict__ C, int K, int lda, int ldb, int ldc)
{
    __shared__ float As[8][132];   // transposed A tile, padded
    __shared__ float Bs[8][132];

    int tid = threadIdx.x;
    int ty = tid >> 4;          // 0..15
    int tx = tid & 15;          // 0..15
    size_t m0 = (size_t)blockIdx.y * 128;
    size_t n0 = (size_t)blockIdx.x * 128;

    int arow = tid >> 1;              // 0..127
    int ak   = (tid & 1) * 4;         // 0 or 4
    int brow = tid >> 5;              // 0..7
    int bcol = (tid & 31) * 4;        // 0..124

    const float* Ap = A + (m0 + arow) * (size_t)lda + ak;
    const float* Bp = B + (size_t)brow * ldb + n0 + bcol;

    float4 a_n = *(const float4*)Ap;
    float4 b_n = *(const float4*)Bp;

    float acc[8][8];
    #pragma unroll
    for (int i = 0; i < 8; i++)
        #pragma unroll
        for (int j = 0; j < 8; j++) acc[i][j] = 0.f;

    for (int k0 = 0; k0 < K; k0 += 8) {
        As[ak + 0][arow] = a_n.x;
        As[ak + 1][arow] = a_n.y;
        As[ak + 2][arow] = a_n.z;
        As[ak + 3][arow] = a_n.w;
        *(float4*)&Bs[brow][bcol] = b_n;
        __syncthreads();

        if (k0 + 8 < K) {
            a_n = *(const float4*)(Ap + k0 + 8);
            b_n = *(const float4*)(Bp + (size_t)(k0 + 8) * ldb);
        }

        #pragma unroll
        for (int kk = 0; kk < 8; kk++) {
            float4 a0 = *(const float4*)&As[kk][ty * 4];
            float4 a1 = *(const float4*)&As[kk][64 + ty * 4];
            float4 b0 = *(const float4*)&Bs[kk][tx * 4];
            float4 b1 = *(const float4*)&Bs[kk][64 + tx * 4];
            float ar[8] = {a0.x, a0.y, a0.z, a0.w, a1.x, a1.y, a1.z, a1.w};
            float br[8] = {b0.x, b0.y, b0.z, b0.w, b1.x, b1.y, b1.z, b1.w};
            #pragma unroll
            for (int i = 0; i < 8; i++)
                #pragma unroll
                for (int j = 0; j < 8; j++)
                    acc[i][j] = fmaf(ar[i], br[j], acc[i][j]);
        }
        __syncthreads();
    }

    #pragma unroll
    for (int i = 0; i < 8; i++) {
        size_t row = m0 + (i < 4 ? (ty * 4 + i) : (64 + ty * 4 + (i - 4)));
        float4 c0 = make_float4(acc[i][0], acc[i][1], acc[i][2], acc[i][3]);
        float4 c1 = make_float4(acc[i][4], acc[i][5], acc[i][6], acc[i][7]);
        *(float4*)&C[row * (size_t)ldc + n0 + tx * 4]      = c0;
        *(float4*)&C[row * (size_t)ldc + n0 + 64 + tx * 4] = c1;
    }
}

// ---------------- RoPE + RMSNorm (q,k) and gated ve add (v), in place -----
// one warp per 64-dim vector; 18 vectors per (b,s): 16 q heads, 1 k, 1 v
__global__ __launch_bounds__(256)
void post_kernel(const float* __restrict__ x, const float* __restrict__ ve,
                 const float* __restrict__ cosb, const float* __restrict__ sinb,
                 const float* __restrict__ Wg, float* __restrict__ qkv)
{
    int wid  = (blockIdx.x * blockDim.x + threadIdx.x) >> 5;
    int lane = threadIdx.x & 31;
    int row = wid / 18;
    int t   = wid - row * 18;
    if (row >= MROWS) return;
    int s = row & (SS - 1);

    if (t < 17) {
        // rope + rmsnorm: q head t (t<16) or k (t==16)
        float* vec = qkv + (size_t)row * NQKV + (t < 16 ? t * 64 : 1024);
        float c  = cosb[s * HALF + lane];
        float sn = sinb[s * HALF + lane];
        float x1 = vec[lane];
        float x2 = vec[lane + 32];
        float y1 = x1 * c + x2 * sn;
        float y2 = x2 * c - x1 * sn;
        float ssum = y1 * y1 + y2 * y2;
        #pragma unroll
        for (int off = 16; off; off >>= 1)
            ssum += __shfl_xor_sync(0xffffffffu, ssum, off);
        float sc = rsqrtf(ssum * (1.0f / 64.0f) + EPSF);
        vec[lane]      = y1 * sc;
        vec[lane + 32] = y2 * sc;
    } else {
        // v += 2*sigmoid(x[:32]@Wg) * ve
        float g = x[(size_t)row * EE + lane] * Wg[lane];
        #pragma unroll
        for (int off = 16; off; off >>= 1)
            g += __shfl_xor_sync(0xffffffffu, g, off);
        float gate = 2.0f / (1.0f + __expf(-g));
        float* vvec = qkv + (size_t)row * NQKV + 1088;
        const float* veb = ve + (size_t)row * DD;
        vvec[lane]      += gate * veb[lane];
        vvec[lane + 32] += gate * veb[lane + 32];
    }
}

// ---------------- windowed-causal flash attention (v3) ----------------
// 128(q) x 64(k) tiles, 256 threads, 4x8 micro-tiles.
// vs v2: same tiles but 2x threads, half the per-thread registers ->
// 16 warps/SM instead of 8 (occupancy was the v2 bottleneck).
#define QT  128
#define KT  64
#define QTP 132
#define KTP 68
// smem floats: Qt 64*QTP + Kt 64*KTP + Vs 64*KTP + Ps 128*KTP
#define ATT_SMEM ((64 * QTP + 64 * KTP + 64 * KTP + 128 * KTP) * sizeof(float))

__global__ __launch_bounds__(256, 2)
void attn_kernel(const float* __restrict__ qkv, float* __restrict__ out,
                 const int* __restrict__ wptr)
{
    extern __shared__ float sm[];
    float* Qt = sm;                      // [64 d][QTP] : Qt[d*QTP + q]
    float* Kt = Qt + 64 * QTP;           // [64 d][KTP] : Kt[d*KTP + k]
    float* Vs = Kt + 64 * KTP;           // [64 k][KTP] : Vs[k*KTP + d]
    float* Ps = Vs + 64 * KTP;           // [128 q][KTP]: Ps[q*KTP + k]

    const int window = *wptr;
    int tid = threadIdx.x;
    int ty = tid >> 3;            // 0..31  (4 q rows each)
    int tx = tid & 7;             // 0..7   (8 k cols / d cols each)
    // heavy-first schedule: high q-tiles have more k-tiles; launch them first
    int qt = (SS / QT - 1) - blockIdx.x;
    int h  = blockIdx.y;
    int b  = blockIdx.z;
    int q0 = qt * QT;
    const float* base = qkv + (size_t)b * SS * NQKV;

    // load Q tile (scaled by D^-1/2), transposed to d-major
    for (int idx = tid; idx < QT * 64; idx += 256) {
        int qq = idx >> 6, d = idx & 63;
        Qt[d * QTP + qq] = base[(size_t)(q0 + qq) * NQKV + h * 64 + d] * 0.125f;
    }

    float o[4][8];
    #pragma unroll
    for (int i = 0; i < 4; i++)
        #pragma unroll
        for (int j = 0; j < 8; j++) o[i][j] = 0.f;
    float mrow[4], lrow[4];
    #pragma unroll
    for (int i = 0; i < 4; i++) { mrow[i] = -INFINITY; lrow[i] = 0.f; }

    int lo = q0 - window + 1; if (lo < 0) lo = 0;
    int t_lo = lo >> 6;
    int t_hi = (q0 + QT - 1) >> 6;

    for (int t = t_lo; t <= t_hi; t++) {
        int k0 = t * 64;
        __syncthreads();   // protect Kt/Vs/Ps from previous iteration (and Qt store)
        for (int idx = tid; idx < 64 * 64; idx += 256) {
            int kk = idx >> 6, d = idx & 63;
            float kv = base[(size_t)(k0 + kk) * NQKV + 1024 + d];
            float vv = base[(size_t)(k0 + kk) * NQKV + 1088 + d];
            Kt[d * KTP + kk] = kv;
            Vs[kk * KTP + d] = vv;
        }
        __syncthreads();

        // S = Q K^T  (rows q = ty*4+i, cols k = tx*8+j)
        float sreg[4][8];
        #pragma unroll
        for (int i = 0; i < 4; i++)
            #pragma unroll
            for (int j = 0; j < 8; j++) sreg[i][j] = 0.f;
        #pragma unroll 8
        for (int d = 0; d < 64; d++) {
            float4 a0 = *(const float4*)&Qt[d * QTP + ty * 4];
            float4 b0 = *(const float4*)&Kt[d * KTP + tx * 8];
            float4 b1 = *(const float4*)&Kt[d * KTP + tx * 8 + 4];
            float ar[4] = {a0.x, a0.y, a0.z, a0.w};
            float br[8] = {b0.x, b0.y, b0.z, b0.w, b1.x, b1.y, b1.z, b1.w};
            #pragma unroll
            for (int i = 0; i < 4; i++)
                #pragma unroll
                for (int j = 0; j < 8; j++)
                    sreg[i][j] = fmaf(ar[i], br[j], sreg[i][j]);
        }

        // mask only boundary tiles
        bool need_mask = (k0 + KT - 1 > q0) || (k0 < q0 + QT - window);
        if (need_mask) {
            #pragma unroll
            for (int i = 0; i < 4; i++) {
                int q = q0 + ty * 4 + i;
                #pragma unroll
                for (int j = 0; j < 8; j++) {
                    int k = k0 + tx * 8 + j;
                    int dist = q - k;
                    if (dist < 0 || dist >= window) sreg[i][j] = -INFINITY;
                }
            }
        }

        // online softmax update (per-row reduce across 8 tx lanes)
        // BRANCH-FREE dead-row handling: every lane executes every shuffle.
        #pragma unroll
        for (int i = 0; i < 4; i++) {
            float pm = fmaxf(fmaxf(fmaxf(sreg[i][0], sreg[i][1]),
                                   fmaxf(sreg[i][2], sreg[i][3])),
                             fmaxf(fmaxf(sreg[i][4], sreg[i][5]),
                                   fmaxf(sreg[i][6], sreg[i][7])));
            #pragma unroll
            for (int off = 4; off; off >>= 1)
                pm = fmaxf(pm, __shfl_xor_sync(0xffffffffu, pm, off));
            float mnew = fmaxf(mrow[i], pm);
            // msafe: if the whole row (incl. history) is masked, use 0 so
            // expf(-inf - 0) = 0 everywhere and no NaNs appear.
            float msafe = (mnew == -INFINITY) ? 0.f : mnew;
            float p[8];
            float rs = 0.f;
            #pragma unroll
            for (int j = 0; j < 8; j++) {
                p[j] = __expf(sreg[i][j] - msafe);   // masked -> 0
                rs += p[j];
            }
            #pragma unroll
            for (int off = 4; off; off >>= 1)
                rs += __shfl_xor_sync(0xffffffffu, rs, off);
            float corr = (mrow[i] == -INFINITY) ? 0.f : __expf(mrow[i] - msafe);
            lrow[i] = lrow[i] * corr + rs;
            mrow[i] = mnew;
            #pragma unroll
            for (int j = 0; j < 8; j++) o[i][j] *= corr;
            float* prow = &Ps[(ty * 4 + i) * KTP + tx * 8];
            *(float4*)prow       = make_float4(p[0], p[1], p[2], p[3]);
            *(float4*)(prow + 4) = make_float4(p[4], p[5], p[6], p[7]);
        }
        __syncwarp();   // Ps row writers/readers share the same 8-lane octet

        // O += P @ V   (rows q = ty*4+i, cols d = tx*8+j)
        #pragma unroll 4
        for (int kk = 0; kk < 64; kk++) {
            float4 v0 = *(const float4*)&Vs[kk * KTP + tx * 8];
            float4 v1 = *(const float4*)&Vs[kk * KTP + tx * 8 + 4];
            float vv[8] = {v0.x, v0.y, v0.z, v0.w, v1.x, v1.y, v1.z, v1.w};
            #pragma unroll
            for (int i = 0; i < 4; i++) {
                float pr = Ps[(ty * 4 + i) * KTP + kk];
                #pragma unroll
                for (int j = 0; j < 8; j++)
                    o[i][j] = fmaf(pr, vv[j], o[i][j]);
            }
        }
    }

    // finalize + write (B,S,H*D)
    #pragma unroll
    for (int i = 0; i < 4; i++) {
        float inv = 1.0f / lrow[i];
        size_t row = (size_t)b * SS + q0 + ty * 4 + i;
        float4 r0 = make_float4(o[i][0] * inv, o[i][1] * inv,
                                o[i][2] * inv, o[i][3] * inv);
        float4 r1 = make_float4(o[i][4] * inv, o[i][5] * inv,
                                o[i][6] * inv, o[i][7] * inv);
        *(float4*)&out[row * EE + h * 64 + tx * 8]     = r0;
        *(float4*)&out[row * EE + h * 64 + tx * 8 + 4] = r1;
    }
}

// ---------------- launch ----------------
extern "C" void kernel_launch(void* const* d_in, const int* in_sizes, int n_in,
                              void* d_out, int out_size)
{
    const float* x    = (const float*)d_in[0];
    const float* ve   = (const float*)d_in[1];
    const float* cosb = (const float*)d_in[2];
    const float* sinb = (const float*)d_in[3];
    const float* Wq   = (const float*)d_in[4];
    const float* Wk   = (const float*)d_in[5];
    const float* Wv   = (const float*)d_in[6];
    const float* Wo   = (const float*)d_in[7];
    const float* Wg   = (const float*)d_in[8];
    const int*   win  = (const int*)d_in[9];
    float* out = (float*)d_out;

    float *wqkv, *qkv, *attn;
    cudaGetSymbolAddress((void**)&wqkv, g_Wqkv);
    cudaGetSymbolAddress((void**)&qkv,  g_qkv);
    cudaGetSymbolAddress((void**)&attn, g_attn);

    cudaFuncSetAttribute(attn_kernel,
                         cudaFuncAttributeMaxDynamicSharedMemorySize,
                         (int)ATT_SMEM);

    // 1. pack weights
    pack_kernel<<<(1024 * NQKV + 255) / 256, 256>>>(Wq, Wk, Wv, wqkv);

    // 2. fused QKV projection: [4096,1024] @ [1024,1152]
    sgemm128<<<dim3(NQKV / 128, MROWS / 128), 256>>>(x, wqkv, qkv,
                                                     1024, 1024, NQKV, NQKV);

    // 3. rope + rmsnorm (q,k), gated ve add (v)
    post_kernel<<<(MROWS * 18) / 8, 256>>>(x, ve, cosb, sinb, Wg, qkv);

    // 4. attention
    attn_kernel<<<dim3(SS / QT, HH, BB), 256, ATT_SMEM>>>(qkv, attn, win);

    // 5. output projection: [4096,1024] @ [1024,1024]
    sgemm128<<<dim3(EE / 128, MROWS / 128), 256>>>(attn, Wo, out,
                                                   1024, 1024, EE, EE);
}

// round 5
// speedup vs baseline: 1.6111x; 1.6111x over previous
#include <cuda_runtime.h>
#include <cuda_bf16.h>
#include <math.h>
#include <stdint.h>

// Problem constants
#define BB   2
#define SS   2048
#define EE   1024
#define HH   16
#define DD   64
#define HALF 32
#define MROWS 4096            // B*S
#define NQKV  1152            // H*D + D + D
#define EPSF  1.1920929e-07f  // finfo(float32).eps

// ---------------- device scratch (static, allocation-free) ----------------
__device__ float g_Wqkv[1024 * NQKV];   // packed [Wq | Wk | Wv], k-major rows
__device__ float g_qkv[MROWS * NQKV];   // projections, later rope/normed in place
__device__ float g_attn[MROWS * EE];    // attention output (B,S,H*D)

// ---------------- pack Wq|Wk|Wv ----------------
__global__ void pack_kernel(const float* __restrict__ Wq,
                            const float* __restrict__ Wk,
                            const float* __restrict__ Wv,
                            float* __restrict__ Wqkv)
{
    int idx = blockIdx.x * blockDim.x + threadIdx.x;
    if (idx >= 1024 * NQKV) return;
    int k = idx / NQKV;
    int n = idx - k * NQKV;
    float v;
    if (n < 1024)       v = Wq[k * 1024 + n];
    else if (n < 1088)  v = Wk[k * 64 + (n - 1024)];
    else                v = Wv[k * 64 + (n - 1088)];
    Wqkv[idx] = v;
}

// ---------------- TF32 tensor-core GEMM ----------------
// C[M,N] = A[M,K] @ B[K,N], fp32 in/out, tf32 mma with fp32 accumulate.
// 128x128x16 block tiles, 256 threads = 8 warps (4m x 2n), warp tile 32x64,
// per warp 2x8 grid of m16n8k8 mma. Smem stride 136 (== 8 mod 32) makes all
// fragment loads bank-conflict-free.
#define GLD 136

__device__ __forceinline__ uint32_t f2tf(float f) {
    uint32_t u;
    asm("cvt.rna.tf32.f32 %0, %1;" : "=r"(u) : "f"(f));
    return u;
}

__device__ __forceinline__ void mma_tf32(float c[4], const uint32_t a[4],
                                         const uint32_t b[2]) {
    asm volatile(
        "mma.sync.aligned.m16n8k8.row.col.f32.tf32.tf32.f32 "
        "{%0,%1,%2,%3}, {%4,%5,%6,%7}, {%8,%9}, {%0,%1,%2,%3};"
        : "+f"(c[0]), "+f"(c[1]), "+f"(c[2]), "+f"(c[3])
        : "r"(a[0]), "r"(a[1]), "r"(a[2]), "r"(a[3]), "r"(b[0]), "r"(b[1]));
}

__global__ __launch_bounds__(256, 2)
void gemm_tf32(const float* __restrict__ A, const float* __restrict__ B,
               float* __restrict__ C, int K, int lda, int ldb, int ldc)
{
    __shared__ uint32_t As[16][GLD];   // As[k][m] (transposed A tile)
    __shared__ uint32_t Bs[16][GLD];   // Bs[k][n]

    int tid  = threadIdx.x;
    int lane = tid & 31;
    int wid  = tid >> 5;
    int wm   = wid & 3;          // warp m index 0..3 (32 rows each)
    int wn   = wid >> 2;         // warp n index 0..1 (64 cols each)
    size_t m0 = (size_t)blockIdx.y * 128;
    size_t n0 = (size_t)blockIdx.x * 128;

    int arow = tid >> 1;         // 0..127
    int ak   = (tid & 1) * 8;    // 0 or 8
    int brow = tid >> 4;         // 0..15
    int bcol = (tid & 15) * 8;   // 0..120

    const float* Ap = A + (m0 + arow) * (size_t)lda + ak;
    const float* Bp = B + (size_t)brow * ldb + n0 + bcol;

    float4 a0n = *(const float4*)Ap;
    float4 a1n = *(const float4*)(Ap + 4);
    float4 b0n = *(const float4*)Bp;
    float4 b1n = *(const float4*)(Bp + 4);

    float acc[2][8][4];
    #pragma unroll
    for (int mt = 0; mt < 2; mt++)
        #pragma unroll
        for (int nt = 0; nt < 8; nt++)
            #pragma unroll
            for (int r = 0; r < 4; r++) acc[mt][nt][r] = 0.f;

    int ar = lane >> 2;          // 0..7
    int ac = lane & 3;           // 0..3

    for (int k0 = 0; k0 < K; k0 += 16) {
        // store current tile (convert to tf32)
        As[ak + 0][arow] = f2tf(a0n.x);
        As[ak + 1][arow] = f2tf(a0n.y);
        As[ak + 2][arow] = f2tf(a0n.z);
        As[ak + 3][arow] = f2tf(a0n.w);
        As[ak + 4][arow] = f2tf(a1n.x);
        As[ak + 5][arow] = f2tf(a1n.y);
        As[ak + 6][arow] = f2tf(a1n.z);
        As[ak + 7][arow] = f2tf(a1n.w);
        *(uint4*)&Bs[brow][bcol] =
            make_uint4(f2tf(b0n.x), f2tf(b0n.y), f2tf(b0n.z), f2tf(b0n.w));
        *(uint4*)&Bs[brow][bcol + 4] =
            make_uint4(f2tf(b1n.x), f2tf(b1n.y), f2tf(b1n.z), f2tf(b1n.w));
        __syncthreads();

        if (k0 + 16 < K) {
            a0n = *(const float4*)(Ap + k0 + 16);
            a1n = *(const float4*)(Ap + k0 + 20);
            b0n = *(const float4*)(Bp + (size_t)(k0 + 16) * ldb);
            b1n = *(const float4*)(Bp + (size_t)(k0 + 16) * ldb + 4);
        }

        #pragma unroll
        for (int kk = 0; kk < 16; kk += 8) {
            uint32_t afr[2][4];
            #pragma unroll
            for (int mt = 0; mt < 2; mt++) {
                int mb = wm * 32 + mt * 16;
                afr[mt][0] = As[kk + ac][mb + ar];
                afr[mt][1] = As[kk + ac][mb + 8 + ar];
                afr[mt][2] = As[kk + 4 + ac][mb + ar];
                afr[mt][3] = As[kk + 4 + ac][mb + 8 + ar];
            }
            uint32_t bfr[8][2];
            #pragma unroll
            for (int nt = 0; nt < 8; nt++) {
                int nb = wn * 64 + nt * 8;
                bfr[nt][0] = Bs[kk + ac][nb + ar];
                bfr[nt][1] = Bs[kk + 4 + ac][nb + ar];
            }
            #pragma unroll
            for (int mt = 0; mt < 2; mt++)
                #pragma unroll
                for (int nt = 0; nt < 8; nt++)
                    mma_tf32(acc[mt][nt], afr[mt], bfr[nt]);
        }
        __syncthreads();
    }

    // epilogue: c0/c1 at (row, col..col+1), c2/c3 at (row+8, col..col+1)
    #pragma unroll
    for (int mt = 0; mt < 2; mt++) {
        size_t row = m0 + wm * 32 + mt * 16 + ar;
        #pragma unroll
        for (int nt = 0; nt < 8; nt++) {
            size_t col = n0 + wn * 64 + nt * 8 + ac * 2;
            *(float2*)&C[row * (size_t)ldc + col] =
                make_float2(acc[mt][nt][0], acc[mt][nt][1]);
            *(float2*)&C[(row + 8) * (size_t)ldc + col] =
                make_float2(acc[mt][nt][2], acc[mt][nt][3]);
        }
    }
}

// ---------------- RoPE + RMSNorm (q,k) and gated ve add (v), in place -----
// one warp per 64-dim vector; 18 vectors per (b,s): 16 q heads, 1 k, 1 v
__global__ __launch_bounds__(256)
void post_kernel(const float* __restrict__ x, const float* __restrict__ ve,
                 const float* __restrict__ cosb, const float* __restrict__ sinb,
                 const float* __restrict__ Wg, float* __restrict__ qkv)
{
    int wid  = (blockIdx.x * blockDim.x + threadIdx.x) >> 5;
    int lane = threadIdx.x & 31;
    int row = wid / 18;
    int t   = wid - row * 18;
    if (row >= MROWS) return;
    int s = row & (SS - 1);

    if (t < 17) {
        // rope + rmsnorm: q head t (t<16) or k (t==16)
        float* vec = qkv + (size_t)row * NQKV + (t < 16 ? t * 64 : 1024);
        float c  = cosb[s * HALF + lane];
        float sn = sinb[s * HALF + lane];
        float x1 = vec[lane];
        float x2 = vec[lane + 32];
        float y1 = x1 * c + x2 * sn;
        float y2 = x2 * c - x1 * sn;
        float ssum = y1 * y1 + y2 * y2;
        #pragma unroll
        for (int off = 16; off; off >>= 1)
            ssum += __shfl_xor_sync(0xffffffffu, ssum, off);
        float sc = rsqrtf(ssum * (1.0f / 64.0f) + EPSF);
        vec[lane]      = y1 * sc;
        vec[lane + 32] = y2 * sc;
    } else {
        // v += 2*sigmoid(x[:32]@Wg) * ve
        float g = x[(size_t)row * EE + lane] * Wg[lane];
        #pragma unroll
        for (int off = 16; off; off >>= 1)
            g += __shfl_xor_sync(0xffffffffu, g, off);
        float gate = 2.0f / (1.0f + __expf(-g));
        float* vvec = qkv + (size_t)row * NQKV + 1088;
        const float* veb = ve + (size_t)row * DD;
        vvec[lane]      += gate * veb[lane];
        vvec[lane + 32] += gate * veb[lane + 32];
    }
}

// ---------------- windowed-causal flash attention (v1 restored) ----------
// 64x64 tiles, 256 threads, 4x4 micro-tiles — the empirically fastest SIMT
// config (497us). Changes vs round-1: branch-free softmax (no divergent
// shfl hazard), heavy-first q-tile order.
#define ATP 68   // padded row stride (floats), float4-aligned
__global__ __launch_bounds__(256)
void attn_kernel(const float* __restrict__ qkv, float* __restrict__ out,
                 const int* __restrict__ wptr)
{
    extern __shared__ float sm[];
    float* Qt = sm;               // [64 d][68] : Qt[d*ATP + q]
    float* Kt = sm + 64 * ATP;    // [64 d][68] : Kt[d*ATP + k]
    float* Vs = sm + 2 * 64 * ATP;// [64 k][68] : Vs[k*ATP + d]
    float* Ps = sm + 3 * 64 * ATP;// [64 q][68] : Ps[q*ATP + k]

    const int window = *wptr;
    int tid = threadIdx.x;
    int ty = tid >> 4;            // 0..15
    int tx = tid & 15;            // 0..15
    int qt = (SS / 64 - 1) - blockIdx.x;   // heavy tiles first
    int h  = blockIdx.y;
    int b  = blockIdx.z;
    int q0 = qt * 64;
    const float* base = qkv + (size_t)b * SS * NQKV;

    // load Q tile (scaled by D^-1/2), transposed to d-major
    for (int idx = tid; idx < 4096; idx += 256) {
        int qq = idx >> 6, d = idx & 63;
        Qt[d * ATP + qq] = base[(size_t)(q0 + qq) * NQKV + h * 64 + d] * 0.125f;
    }

    float o[4][4];
    #pragma unroll
    for (int i = 0; i < 4; i++)
        #pragma unroll
        for (int j = 0; j < 4; j++) o[i][j] = 0.f;
    float mrow[4], lrow[4];
    #pragma unroll
    for (int i = 0; i < 4; i++) { mrow[i] = -INFINITY; lrow[i] = 0.f; }

    int lo = q0 - window + 1; if (lo < 0) lo = 0;
    int t_lo = lo >> 6;

    for (int t = t_lo; t <= qt; t++) {
        int k0 = t * 64;
        __syncthreads();   // protect Kt/Vs/Ps from previous iteration (and Qt store)
        for (int idx = tid; idx < 4096; idx += 256) {
            int kk = idx >> 6, d = idx & 63;
            Kt[d * ATP + kk] = base[(size_t)(k0 + kk) * NQKV + 1024 + d];
            Vs[kk * ATP + d] = base[(size_t)(k0 + kk) * NQKV + 1088 + d];
        }
        __syncthreads();

        // S = Q K^T  (rows q = ty*4+i, cols k = tx*4+j)
        float sreg[4][4];
        #pragma unroll
        for (int i = 0; i < 4; i++)
            #pragma unroll
            for (int j = 0; j < 4; j++) sreg[i][j] = 0.f;
        #pragma unroll 16
        for (int d = 0; d < 64; d++) {
            float4 a = *(const float4*)&Qt[d * ATP + ty * 4];
            float4 kb = *(const float4*)&Kt[d * ATP + tx * 4];
            float av[4] = {a.x, a.y, a.z, a.w};
            float kv[4] = {kb.x, kb.y, kb.z, kb.w};
            #pragma unroll
            for (int i = 0; i < 4; i++)
                #pragma unroll
                for (int j = 0; j < 4; j++)
                    sreg[i][j] = fmaf(av[i], kv[j], sreg[i][j]);
        }

        // mask
        #pragma unroll
        for (int i = 0; i < 4; i++) {
            int q = q0 + ty * 4 + i;
            #pragma unroll
            for (int j = 0; j < 4; j++) {
                int k = k0 + tx * 4 + j;
                int dist = q - k;
                if (dist < 0 || dist >= window) sreg[i][j] = -INFINITY;
            }
        }

        // online softmax update (per-row reduce across 16 tx lanes)
        // branch-free dead-row handling: every lane runs every shuffle
        #pragma unroll
        for (int i = 0; i < 4; i++) {
            float pm = fmaxf(fmaxf(sreg[i][0], sreg[i][1]),
                             fmaxf(sreg[i][2], sreg[i][3]));
            #pragma unroll
            for (int off = 8; off; off >>= 1)
                pm = fmaxf(pm, __shfl_xor_sync(0xffffffffu, pm, off));
            float mnew = fmaxf(mrow[i], pm);
            float msafe = (mnew == -INFINITY) ? 0.f : mnew;
            float p0 = __expf(sreg[i][0] - msafe);
            float p1 = __expf(sreg[i][1] - msafe);
            float p2 = __expf(sreg[i][2] - msafe);
            float p3 = __expf(sreg[i][3] - msafe);
            float rs = p0 + p1 + p2 + p3;
            #pragma unroll
            for (int off = 8; off; off >>= 1)
                rs += __shfl_xor_sync(0xffffffffu, rs, off);
            float corr = (mrow[i] == -INFINITY) ? 0.f : __expf(mrow[i] - msafe);
            lrow[i] = lrow[i] * corr + rs;
            mrow[i] = mnew;
            #pragma unroll
            for (int j = 0; j < 4; j++) o[i][j] *= corr;
            *(float4*)&Ps[(ty * 4 + i) * ATP + tx * 4] =
                make_float4(p0, p1, p2, p3);
        }
        __syncthreads();

        // O += P @ V   (rows q = ty*4+i, cols d = tx*4+j)
        #pragma unroll 8
        for (int kk = 0; kk < 64; kk++) {
            float4 v = *(const float4*)&Vs[kk * ATP + tx * 4];
            float vv[4] = {v.x, v.y, v.z, v.w};
            float pr0 = Ps[(ty * 4 + 0) * ATP + kk];
            float pr1 = Ps[(ty * 4 + 1) * ATP + kk];
            float pr2 = Ps[(ty * 4 + 2) * ATP + kk];
            float pr3 = Ps[(ty * 4 + 3) * ATP + kk];
            #pragma unroll
            for (int j = 0; j < 4; j++) {
                o[0][j] = fmaf(pr0, vv[j], o[0][j]);
                o[1][j] = fmaf(pr1, vv[j], o[1][j]);
                o[2][j] = fmaf(pr2, vv[j], o[2][j]);
                o[3][j] = fmaf(pr3, vv[j], o[3][j]);
            }
        }
    }

    // finalize + write (B,S,H*D)
    #pragma unroll
    for (int i = 0; i < 4; i++) {
        float inv = 1.0f / lrow[i];
        float4 r = make_float4(o[i][0] * inv, o[i][1] * inv,
                               o[i][2] * inv, o[i][3] * inv);
        size_t row = (size_t)b * SS + q0 + ty * 4 + i;
        *(float4*)&out[row * EE + h * 64 + tx * 4] = r;
    }
}

#define ATT_SMEM (4 * 64 * ATP * sizeof(float))   // 69,632 B

// ---------------- launch ----------------
extern "C" void kernel_launch(void* const* d_in, const int* in_sizes, int n_in,
                              void* d_out, int out_size)
{
    const float* x    = (const float*)d_in[0];
    const float* ve   = (const float*)d_in[1];
    const float* cosb = (const float*)d_in[2];
    const float* sinb = (const float*)d_in[3];
    const float* Wq   = (const float*)d_in[4];
    const float* Wk   = (const float*)d_in[5];
    const float* Wv   = (const float*)d_in[6];
    const float* Wo   = (const float*)d_in[7];
    const float* Wg   = (const float*)d_in[8];
    const int*   win  = (const int*)d_in[9];
    float* out = (float*)d_out;

    float *wqkv, *qkv, *attn;
    cudaGetSymbolAddress((void**)&wqkv, g_Wqkv);
    cudaGetSymbolAddress((void**)&qkv,  g_qkv);
    cudaGetSymbolAddress((void**)&attn, g_attn);

    cudaFuncSetAttribute(attn_kernel,
                         cudaFuncAttributeMaxDynamicSharedMemorySize,
                         (int)ATT_SMEM);

    // 1. pack weights
    pack_kernel<<<(1024 * NQKV + 255) / 256, 256>>>(Wq, Wk, Wv, wqkv);

    // 2. fused QKV projection: [4096,1024] @ [1024,1152]  (tf32 tensor core)
    gemm_tf32<<<dim3(NQKV / 128, MROWS / 128), 256>>>(x, wqkv, qkv,
                                                      1024, 1024, NQKV, NQKV);

    // 3. rope + rmsnorm (q,k), gated ve add (v)
    post_kernel<<<(MROWS * 18) / 8, 256>>>(x, ve, cosb, sinb, Wg, qkv);

    // 4. attention
    attn_kernel<<<dim3(SS / 64, HH, BB), 256, ATT_SMEM>>>(qkv, attn, win);

    // 5. output projection: [4096,1024] @ [1024,1024]  (tf32 tensor core)
    gemm_tf32<<<dim3(EE / 128, MROWS / 128), 256>>>(attn, Wo, out,
                                                    1024, 1024, EE, EE);
}

// round 9
// speedup vs baseline: 2.3583x; 1.4637x over previous
#include <cuda_runtime.h>
#include <cuda_bf16.h>
#include <math.h>
#include <stdint.h>

// Problem constants
#define BB   2
#define SS   2048
#define EE   1024
#define HH   16
#define DD   64
#define HALF 32
#define MROWS 4096            // B*S
#define NQKV  1152            // H*D + D + D
#define EPSF  1.1920929e-07f  // finfo(float32).eps

// ---------------- device scratch (static, allocation-free) ----------------
__device__ float g_Wqkv[1024 * NQKV];   // packed [Wq | Wk | Wv], k-major rows
__device__ float g_qkv[MROWS * NQKV];   // projections, later rope/normed in place
__device__ float g_attn[MROWS * EE];    // attention output (B,S,H*D)

// ---------------- tf32 helpers ----------------
__device__ __forceinline__ uint32_t f2tf(float f) {
    uint32_t u;
    asm("cvt.rna.tf32.f32 %0, %1;" : "=r"(u) : "f"(f));
    return u;
}

__device__ __forceinline__ void mma_tf32(float c[4], const uint32_t a[4],
                                         const uint32_t b[2]) {
    asm volatile(
        "mma.sync.aligned.m16n8k8.row.col.f32.tf32.tf32.f32 "
        "{%0,%1,%2,%3}, {%4,%5,%6,%7}, {%8,%9}, {%0,%1,%2,%3};"
        : "+f"(c[0]), "+f"(c[1]), "+f"(c[2]), "+f"(c[3])
        : "r"(a[0]), "r"(a[1]), "r"(a[2]), "r"(a[3]), "r"(b[0]), "r"(b[1]));
}

// ---------------- pack Wq|Wk|Wv ----------------
__global__ void pack_kernel(const float* __restrict__ Wq,
                            const float* __restrict__ Wk,
                            const float* __restrict__ Wv,
                            float* __restrict__ Wqkv)
{
    int idx = blockIdx.x * blockDim.x + threadIdx.x;
    if (idx >= 1024 * NQKV) return;
    int k = idx / NQKV;
    int n = idx - k * NQKV;
    float v;
    if (n < 1024)       v = Wq[k * 1024 + n];
    else if (n < 1088)  v = Wk[k * 64 + (n - 1024)];
    else                v = Wv[k * 64 + (n - 1088)];
    Wqkv[idx] = v;
}

// ---------------- TF32 tensor-core GEMM (round-5 proven) ----------------
#define GLD 136

__global__ __launch_bounds__(256, 2)
void gemm_tf32(const float* __restrict__ A, const float* __restrict__ B,
               float* __restrict__ C, int K, int lda, int ldb, int ldc)
{
    __shared__ uint32_t As[16][GLD];   // As[k][m] (transposed A tile)
    __shared__ uint32_t Bs[16][GLD];   // Bs[k][n]

    int tid  = threadIdx.x;
    int lane = tid & 31;
    int wid  = tid >> 5;
    int wm   = wid & 3;          // warp m index 0..3 (32 rows each)
    int wn   = wid >> 2;         // warp n index 0..1 (64 cols each)
    size_t m0 = (size_t)blockIdx.y * 128;
    size_t n0 = (size_t)blockIdx.x * 128;

    int arow = tid >> 1;         // 0..127
    int ak   = (tid & 1) * 8;    // 0 or 8
    int brow = tid >> 4;         // 0..15
    int bcol = (tid & 15) * 8;   // 0..120

    const float* Ap = A + (m0 + arow) * (size_t)lda + ak;
    const float* Bp = B + (size_t)brow * ldb + n0 + bcol;

    float4 a0n = *(const float4*)Ap;
    float4 a1n = *(const float4*)(Ap + 4);
    float4 b0n = *(const float4*)Bp;
    float4 b1n = *(const float4*)(Bp + 4);

    float acc[2][8][4];
    #pragma unroll
    for (int mt = 0; mt < 2; mt++)
        #pragma unroll
        for (int nt = 0; nt < 8; nt++)
            #pragma unroll
            for (int r = 0; r < 4; r++) acc[mt][nt][r] = 0.f;

    int ar = lane >> 2;          // 0..7
    int ac = lane & 3;           // 0..3

    for (int k0 = 0; k0 < K; k0 += 16) {
        As[ak + 0][arow] = f2tf(a0n.x);
        As[ak + 1][arow] = f2tf(a0n.y);
        As[ak + 2][arow] = f2tf(a0n.z);
        As[ak + 3][arow] = f2tf(a0n.w);
        As[ak + 4][arow] = f2tf(a1n.x);
        As[ak + 5][arow] = f2tf(a1n.y);
        As[ak + 6][arow] = f2tf(a1n.z);
        As[ak + 7][arow] = f2tf(a1n.w);
        *(uint4*)&Bs[brow][bcol] =
            make_uint4(f2tf(b0n.x), f2tf(b0n.y), f2tf(b0n.z), f2tf(b0n.w));
        *(uint4*)&Bs[brow][bcol + 4] =
            make_uint4(f2tf(b1n.x), f2tf(b1n.y), f2tf(b1n.z), f2tf(b1n.w));
        __syncthreads();

        if (k0 + 16 < K) {
            a0n = *(const float4*)(Ap + k0 + 16);
            a1n = *(const float4*)(Ap + k0 + 20);
            b0n = *(const float4*)(Bp + (size_t)(k0 + 16) * ldb);
            b1n = *(const float4*)(Bp + (size_t)(k0 + 16) * ldb + 4);
        }

        #pragma unroll
        for (int kk = 0; kk < 16; kk += 8) {
            uint32_t afr[2][4];
            #pragma unroll
            for (int mt = 0; mt < 2; mt++) {
                int mb = wm * 32 + mt * 16;
                afr[mt][0] = As[kk + ac][mb + ar];
                afr[mt][1] = As[kk + ac][mb + 8 + ar];
                afr[mt][2] = As[kk + 4 + ac][mb + ar];
                afr[mt][3] = As[kk + 4 + ac][mb + 8 + ar];
            }
            uint32_t bfr[8][2];
            #pragma unroll
            for (int nt = 0; nt < 8; nt++) {
                int nb = wn * 64 + nt * 8;
                bfr[nt][0] = Bs[kk + ac][nb + ar];
                bfr[nt][1] = Bs[kk + 4 + ac][nb + ar];
            }
            #pragma unroll
            for (int mt = 0; mt < 2; mt++)
                #pragma unroll
                for (int nt = 0; nt < 8; nt++)
                    mma_tf32(acc[mt][nt], afr[mt], bfr[nt]);
        }
        __syncthreads();
    }

    #pragma unroll
    for (int mt = 0; mt < 2; mt++) {
        size_t row = m0 + wm * 32 + mt * 16 + ar;
        #pragma unroll
        for (int nt = 0; nt < 8; nt++) {
            size_t col = n0 + wn * 64 + nt * 8 + ac * 2;
            *(float2*)&C[row * (size_t)ldc + col] =
                make_float2(acc[mt][nt][0], acc[mt][nt][1]);
            *(float2*)&C[(row + 8) * (size_t)ldc + col] =
                make_float2(acc[mt][nt][2], acc[mt][nt][3]);
        }
    }
}

// ---------------- RoPE + RMSNorm (q,k) and gated ve add (v), in place -----
__global__ __launch_bounds__(256)
void post_kernel(const float* __restrict__ x, const float* __restrict__ ve,
                 const float* __restrict__ cosb, const float* __restrict__ sinb,
                 const float* __restrict__ Wg, float* __restrict__ qkv)
{
    int wid  = (blockIdx.x * blockDim.x + threadIdx.x) >> 5;
    int lane = threadIdx.x & 31;
    int row = wid / 18;
    int t   = wid - row * 18;
    if (row >= MROWS) return;
    int s = row & (SS - 1);

    if (t < 17) {
        float* vec = qkv + (size_t)row * NQKV + (t < 16 ? t * 64 : 1024);
        float c  = cosb[s * HALF + lane];
        float sn = sinb[s * HALF + lane];
        float x1 = vec[lane];
        float x2 = vec[lane + 32];
        float y1 = x1 * c + x2 * sn;
        float y2 = x2 * c - x1 * sn;
        float ssum = y1 * y1 + y2 * y2;
        #pragma unroll
        for (int off = 16; off; off >>= 1)
            ssum += __shfl_xor_sync(0xffffffffu, ssum, off);
        float sc = rsqrtf(ssum * (1.0f / 64.0f) + EPSF);
        vec[lane]      = y1 * sc;
        vec[lane + 32] = y2 * sc;
    } else {
        float g = x[(size_t)row * EE + lane] * Wg[lane];
        #pragma unroll
        for (int off = 16; off; off >>= 1)
            g += __shfl_xor_sync(0xffffffffu, g, off);
        float gate = 2.0f / (1.0f + __expf(-g));
        float* vvec = qkv + (size_t)row * NQKV + 1088;
        const float* veb = ve + (size_t)row * DD;
        vvec[lane]      += gate * veb[lane];
        vvec[lane + 32] += gate * veb[lane + 32];
    }
}

// ---------------- windowed-causal flash attention, tf32 tensor cores -----
// 64q x 64k tiles, 256 threads = 8 warps: (4 m-blocks of 16q) x (2 col-halves
// of 32). QK^T and P@V on mma.m16n8k8.tf32; softmax fp32 in registers with
// cross-half row stats exchanged through smem. All tiles stride 72 (== 8 mod
// 32 banks -> conflict-free fragment loads).
#define TS 72
// smem words: Qt,Kt,Vs,Ps 4*64*72 + hmax/hsum 2*2*64
#define ATT_SMEM ((4 * 64 * TS + 4 * 64) * 4)

__global__ __launch_bounds__(256)
void attn_kernel(const float* __restrict__ qkv, float* __restrict__ out,
                 const int* __restrict__ wptr)
{
    extern __shared__ uint32_t smu[];
    uint32_t* Qt = smu;                  // [64 d][TS]   : Qt[d*TS + q]   (tf32)
    uint32_t* Kt = Qt + 64 * TS;         // [64 d][TS]   : Kt[d*TS + key] (tf32)
    uint32_t* Vs = Kt + 64 * TS;         // [64 key][TS] : Vs[key*TS + d] (tf32)
    uint32_t* Ps = Vs + 64 * TS;         // [64 key][TS] : Ps[key*TS + q] (tf32)
    float* hmax = (float*)(Ps + 64 * TS);   // [2][64]
    float* hsum = hmax + 2 * 64;            // [2][64]

    const int window = *wptr;
    int tid  = threadIdx.x;
    int lane = tid & 31;
    int wid  = tid >> 5;
    int mb   = (wid & 3) * 16;    // warp's q-block base (16 rows)
    int half = wid >> 2;          // 0/1: which 32-col half (keys in QK, d in PV)
    int kb   = half * 32;
    int ar   = lane >> 2;         // 0..7
    int ac   = lane & 3;          // 0..3
    int r0   = mb + ar;           // this thread's q rows within the tile
    int r1   = r0 + 8;

    int qt = (SS / 64 - 1) - blockIdx.x;   // heavy tiles first
    int h  = blockIdx.y;
    int b  = blockIdx.z;
    int q0 = qt * 64;
    const float* base = qkv + (size_t)b * SS * NQKV;

    // load Q tile (scaled, tf32), transposed to [d][q]
    for (int idx = tid; idx < 4096; idx += 256) {
        int qq = idx >> 6, d = idx & 63;
        Qt[d * TS + qq] =
            f2tf(base[(size_t)(q0 + qq) * NQKV + h * 64 + d] * 0.125f);
    }

    float of[4][4];
    #pragma unroll
    for (int nb = 0; nb < 4; nb++)
        #pragma unroll
        for (int c = 0; c < 4; c++) of[nb][c] = 0.f;
    float m0r = -INFINITY, m1r = -INFINITY, l0r = 0.f, l1r = 0.f;

    int lo = q0 - window + 1; if (lo < 0) lo = 0;
    int t_lo = lo >> 6;

    for (int t = t_lo; t <= qt; t++) {
        int k0 = t * 64;
        __syncthreads();   // protect tiles/stats from previous iteration
        for (int idx = tid; idx < 4096; idx += 256) {
            int kk = idx >> 6, d = idx & 63;
            Kt[d * TS + kk]  = f2tf(base[(size_t)(k0 + kk) * NQKV + 1024 + d]);
            Vs[kk * TS + d]  = f2tf(base[(size_t)(k0 + kk) * NQKV + 1088 + d]);
        }
        __syncthreads();

        // ---- S = Q K^T on tensor cores ----
        float sf[4][4];
        #pragma unroll
        for (int nb = 0; nb < 4; nb++)
            #pragma unroll
            for (int c = 0; c < 4; c++) sf[nb][c] = 0.f;
        #pragma unroll
        for (int kk = 0; kk < 64; kk += 8) {
            uint32_t afr[4];
            afr[0] = Qt[(kk + ac) * TS + r0];
            afr[1] = Qt[(kk + ac) * TS + r1];
            afr[2] = Qt[(kk + 4 + ac) * TS + r0];
            afr[3] = Qt[(kk + 4 + ac) * TS + r1];
            #pragma unroll
            for (int nb = 0; nb < 4; nb++) {
                uint32_t bfr[2];
                bfr[0] = Kt[(kk + ac) * TS + kb + nb * 8 + ar];
                bfr[1] = Kt[(kk + 4 + ac) * TS + kb + nb * 8 + ar];
                mma_tf32(sf[nb], afr, bfr);
            }
        }

        // ---- mask ----
        int qg0 = q0 + r0, qg1 = q0 + r1;
        #pragma unroll
        for (int nb = 0; nb < 4; nb++) {
            int kg = k0 + kb + nb * 8 + ac * 2;
            #pragma unroll
            for (int cc = 0; cc < 2; cc++) {
                int kk = kg + cc;
                int d0 = qg0 - kk, d1 = qg1 - kk;
                if (d0 < 0 || d0 >= window) sf[nb][cc]     = -INFINITY;
                if (d1 < 0 || d1 >= window) sf[nb][2 + cc] = -INFINITY;
            }
        }

        // ---- online softmax (fp32) ----
        float pm0 = -INFINITY, pm1 = -INFINITY;
        #pragma unroll
        for (int nb = 0; nb < 4; nb++) {
            pm0 = fmaxf(pm0, fmaxf(sf[nb][0], sf[nb][1]));
            pm1 = fmaxf(pm1, fmaxf(sf[nb][2], sf[nb][3]));
        }
        pm0 = fmaxf(pm0, __shfl_xor_sync(0xffffffffu, pm0, 1));
        pm0 = fmaxf(pm0, __shfl_xor_sync(0xffffffffu, pm0, 2));
        pm1 = fmaxf(pm1, __shfl_xor_sync(0xffffffffu, pm1, 1));
        pm1 = fmaxf(pm1, __shfl_xor_sync(0xffffffffu, pm1, 2));
        if (ac == 0) {
            hmax[half * 64 + r0] = pm0;
            hmax[half * 64 + r1] = pm1;
        }
        __syncthreads();
        float mnew0 = fmaxf(m0r, fmaxf(pm0, hmax[(1 - half) * 64 + r0]));
        float mnew1 = fmaxf(m1r, fmaxf(pm1, hmax[(1 - half) * 64 + r1]));
        float ms0 = (mnew0 == -INFINITY) ? 0.f : mnew0;
        float ms1 = (mnew1 == -INFINITY) ? 0.f : mnew1;

        float hs0 = 0.f, hs1 = 0.f;
        #pragma unroll
        for (int nb = 0; nb < 4; nb++) {
            int kcol = kb + nb * 8 + ac * 2;
            float p0 = __expf(sf[nb][0] - ms0);
            float p1 = __expf(sf[nb][1] - ms0);
            float p2 = __expf(sf[nb][2] - ms1);
            float p3 = __expf(sf[nb][3] - ms1);
            hs0 += p0 + p1;
            hs1 += p2 + p3;
            Ps[kcol * TS + r0]       = f2tf(p0);
            Ps[(kcol + 1) * TS + r0] = f2tf(p1);
            Ps[kcol * TS + r1]       = f2tf(p2);
            Ps[(kcol + 1) * TS + r1] = f2tf(p3);
        }
        hs0 += __shfl_xor_sync(0xffffffffu, hs0, 1);
        hs0 += __shfl_xor_sync(0xffffffffu, hs0, 2);
        hs1 += __shfl_xor_sync(0xffffffffu, hs1, 1);
        hs1 += __shfl_xor_sync(0xffffffffu, hs1, 2);
        if (ac == 0) {
            hsum[half * 64 + r0] = hs0;
            hsum[half * 64 + r1] = hs1;
        }
        float corr0 = (m0r == -INFINITY) ? 0.f : __expf(m0r - ms0);
        float corr1 = (m1r == -INFINITY) ? 0.f : __expf(m1r - ms1);
        #pragma unroll
        for (int nb = 0; nb < 4; nb++) {
            of[nb][0] *= corr0; of[nb][1] *= corr0;
            of[nb][2] *= corr1; of[nb][3] *= corr1;
        }
        m0r = mnew0; m1r = mnew1;
        __syncthreads();   // Ps + hsum visible to all warps
        l0r = l0r * corr0 + hsum[r0] + hsum[64 + r0];
        l1r = l1r * corr1 + hsum[r1] + hsum[64 + r1];

        // ---- O += P @ V on tensor cores ----
        #pragma unroll
        for (int kk = 0; kk < 64; kk += 8) {
            uint32_t afr[4];
            afr[0] = Ps[(kk + ac) * TS + r0];
            afr[1] = Ps[(kk + ac) * TS + r1];
            afr[2] = Ps[(kk + 4 + ac) * TS + r0];
            afr[3] = Ps[(kk + 4 + ac) * TS + r1];
            #pragma unroll
            for (int nb = 0; nb < 4; nb++) {
                uint32_t bfr[2];
                bfr[0] = Vs[(kk + ac) * TS + kb + nb * 8 + ar];
                bfr[1] = Vs[(kk + 4 + ac) * TS + kb + nb * 8 + ar];
                mma_tf32(of[nb], afr, bfr);
            }
        }
    }

    // ---- finalize + write (B,S,H*D) ----
    float inv0 = 1.0f / l0r;
    float inv1 = 1.0f / l1r;
    size_t row0 = (size_t)b * SS + q0 + r0;
    size_t row1 = (size_t)b * SS + q0 + r1;
    #pragma unroll
    for (int nb = 0; nb < 4; nb++) {
        size_t col = h * 64 + kb + nb * 8 + ac * 2;
        *(float2*)&out[row0 * EE + col] =
            make_float2(of[nb][0] * inv0, of[nb][1] * inv0);
        *(float2*)&out[row1 * EE + col] =
            make_float2(of[nb][2] * inv1, of[nb][3] * inv1);
    }
}

// ---------------- launch ----------------
extern "C" void kernel_launch(void* const* d_in, const int* in_sizes, int n_in,
                              void* d_out, int out_size)
{
    const float* x    = (const float*)d_in[0];
    const float* ve   = (const float*)d_in[1];
    const float* cosb = (const float*)d_in[2];
    const float* sinb = (const float*)d_in[3];
    const float* Wq   = (const float*)d_in[4];
    const float* Wk   = (const float*)d_in[5];
    const float* Wv   = (const float*)d_in[6];
    const float* Wo   = (const float*)d_in[7];
    const float* Wg   = (const float*)d_in[8];
    const int*   win  = (const int*)d_in[9];
    float* out = (float*)d_out;

    float *wqkv, *qkv, *attn;
    cudaGetSymbolAddress((void**)&wqkv, g_Wqkv);
    cudaGetSymbolAddress((void**)&qkv,  g_qkv);
    cudaGetSymbolAddress((void**)&attn, g_attn);

    cudaFuncSetAttribute(attn_kernel,
                         cudaFuncAttributeMaxDynamicSharedMemorySize,
                         (int)ATT_SMEM);

    // 1. pack weights
    pack_kernel<<<(1024 * NQKV + 255) / 256, 256>>>(Wq, Wk, Wv, wqkv);

    // 2. fused QKV projection: [4096,1024] @ [1024,1152]  (tf32 tensor core)
    gemm_tf32<<<dim3(NQKV / 128, MROWS / 128), 256>>>(x, wqkv, qkv,
                                                      1024, 1024, NQKV, NQKV);

    // 3. rope + rmsnorm (q,k), gated ve add (v)
    post_kernel<<<(MROWS * 18) / 8, 256>>>(x, ve, cosb, sinb, Wg, qkv);

    // 4. attention (tf32 tensor core)
    attn_kernel<<<dim3(SS / 64, HH, BB), 256, ATT_SMEM>>>(qkv, attn, win);

    // 5. output projection: [4096,1024] @ [1024,1024]  (tf32 tensor core)
    gemm_tf32<<<dim3(EE / 128, MROWS / 128), 256>>>(attn, Wo, out,
                                                    1024, 1024, EE, EE);
}

// round 10
// speedup vs baseline: 2.5389x; 1.0766x over previous
#include <cuda_runtime.h>
#include <cuda_bf16.h>
#include <math.h>
#include <stdint.h>

// Problem constants
#define BB   2
#define SS   2048
#define EE   1024
#define HH   16
#define DD   64
#define HALF 32
#define MROWS 4096            // B*S
#define NQKV  1152            // H*D + D + D
#define EPSF  1.1920929e-07f  // finfo(float32).eps

// ---------------- device scratch (static, allocation-free) ----------------
__device__ float g_Wqkv[1024 * NQKV];   // packed [Wq | Wk | Wv], k-major rows
__device__ float g_qkv[MROWS * NQKV];   // projections, later rope/normed in place
__device__ float g_attn[MROWS * EE];    // attention output (B,S,H*D)

// ---------------- tf32 helpers ----------------
__device__ __forceinline__ uint32_t f2tf(float f) {
    uint32_t u;
    asm("cvt.rna.tf32.f32 %0, %1;" : "=r"(u) : "f"(f));
    return u;
}

__device__ __forceinline__ void mma_tf32(float c[4], const uint32_t a[4],
                                         const uint32_t b[2]) {
    asm volatile(
        "mma.sync.aligned.m16n8k8.row.col.f32.tf32.tf32.f32 "
        "{%0,%1,%2,%3}, {%4,%5,%6,%7}, {%8,%9}, {%0,%1,%2,%3};"
        : "+f"(c[0]), "+f"(c[1]), "+f"(c[2]), "+f"(c[3])
        : "r"(a[0]), "r"(a[1]), "r"(a[2]), "r"(a[3]), "r"(b[0]), "r"(b[1]));
}

// ---------------- pack Wq|Wk|Wv ----------------
__global__ void pack_kernel(const float* __restrict__ Wq,
                            const float* __restrict__ Wk,
                            const float* __restrict__ Wv,
                            float* __restrict__ Wqkv)
{
    int idx = blockIdx.x * blockDim.x + threadIdx.x;
    if (idx >= 1024 * NQKV) return;
    int k = idx / NQKV;
    int n = idx - k * NQKV;
    float v;
    if (n < 1024)       v = Wq[k * 1024 + n];
    else if (n < 1088)  v = Wk[k * 64 + (n - 1024)];
    else                v = Wv[k * 64 + (n - 1088)];
    Wqkv[idx] = v;
}

// ---------------- TF32 tensor-core GEMM (round-5 proven) ----------------
#define GLD 136

__global__ __launch_bounds__(256, 2)
void gemm_tf32(const float* __restrict__ A, const float* __restrict__ B,
               float* __restrict__ C, int K, int lda, int ldb, int ldc)
{
    __shared__ uint32_t As[16][GLD];   // As[k][m] (transposed A tile)
    __shared__ uint32_t Bs[16][GLD];   // Bs[k][n]

    int tid  = threadIdx.x;
    int lane = tid & 31;
    int wid  = tid >> 5;
    int wm   = wid & 3;          // warp m index 0..3 (32 rows each)
    int wn   = wid >> 2;         // warp n index 0..1 (64 cols each)
    size_t m0 = (size_t)blockIdx.y * 128;
    size_t n0 = (size_t)blockIdx.x * 128;

    int arow = tid >> 1;         // 0..127
    int ak   = (tid & 1) * 8;    // 0 or 8
    int brow = tid >> 4;         // 0..15
    int bcol = (tid & 15) * 8;   // 0..120

    const float* Ap = A + (m0 + arow) * (size_t)lda + ak;
    const float* Bp = B + (size_t)brow * ldb + n0 + bcol;

    float4 a0n = *(const float4*)Ap;
    float4 a1n = *(const float4*)(Ap + 4);
    float4 b0n = *(const float4*)Bp;
    float4 b1n = *(const float4*)(Bp + 4);

    float acc[2][8][4];
    #pragma unroll
    for (int mt = 0; mt < 2; mt++)
        #pragma unroll
        for (int nt = 0; nt < 8; nt++)
            #pragma unroll
            for (int r = 0; r < 4; r++) acc[mt][nt][r] = 0.f;

    int ar = lane >> 2;          // 0..7
    int ac = lane & 3;           // 0..3

    for (int k0 = 0; k0 < K; k0 += 16) {
        As[ak + 0][arow] = f2tf(a0n.x);
        As[ak + 1][arow] = f2tf(a0n.y);
        As[ak + 2][arow] = f2tf(a0n.z);
        As[ak + 3][arow] = f2tf(a0n.w);
        As[ak + 4][arow] = f2tf(a1n.x);
        As[ak + 5][arow] = f2tf(a1n.y);
        As[ak + 6][arow] = f2tf(a1n.z);
        As[ak + 7][arow] = f2tf(a1n.w);
        *(uint4*)&Bs[brow][bcol] =
            make_uint4(f2tf(b0n.x), f2tf(b0n.y), f2tf(b0n.z), f2tf(b0n.w));
        *(uint4*)&Bs[brow][bcol + 4] =
            make_uint4(f2tf(b1n.x), f2tf(b1n.y), f2tf(b1n.z), f2tf(b1n.w));
        __syncthreads();

        if (k0 + 16 < K) {
            a0n = *(const float4*)(Ap + k0 + 16);
            a1n = *(const float4*)(Ap + k0 + 20);
            b0n = *(const float4*)(Bp + (size_t)(k0 + 16) * ldb);
            b1n = *(const float4*)(Bp + (size_t)(k0 + 16) * ldb + 4);
        }

        #pragma unroll
        for (int kk = 0; kk < 16; kk += 8) {
            uint32_t afr[2][4];
            #pragma unroll
            for (int mt = 0; mt < 2; mt++) {
                int mb = wm * 32 + mt * 16;
                afr[mt][0] = As[kk + ac][mb + ar];
                afr[mt][1] = As[kk + ac][mb + 8 + ar];
                afr[mt][2] = As[kk + 4 + ac][mb + ar];
                afr[mt][3] = As[kk + 4 + ac][mb + 8 + ar];
            }
            uint32_t bfr[8][2];
            #pragma unroll
            for (int nt = 0; nt < 8; nt++) {
                int nb = wn * 64 + nt * 8;
                bfr[nt][0] = Bs[kk + ac][nb + ar];
                bfr[nt][1] = Bs[kk + 4 + ac][nb + ar];
            }
            #pragma unroll
            for (int mt = 0; mt < 2; mt++)
                #pragma unroll
                for (int nt = 0; nt < 8; nt++)
                    mma_tf32(acc[mt][nt], afr[mt], bfr[nt]);
        }
        __syncthreads();
    }

    #pragma unroll
    for (int mt = 0; mt < 2; mt++) {
        size_t row = m0 + wm * 32 + mt * 16 + ar;
        #pragma unroll
        for (int nt = 0; nt < 8; nt++) {
            size_t col = n0 + wn * 64 + nt * 8 + ac * 2;
            *(float2*)&C[row * (size_t)ldc + col] =
                make_float2(acc[mt][nt][0], acc[mt][nt][1]);
            *(float2*)&C[(row + 8) * (size_t)ldc + col] =
                make_float2(acc[mt][nt][2], acc[mt][nt][3]);
        }
    }
}

// ---------------- RoPE + RMSNorm (q,k) and gated ve add (v), in place -----
__global__ __launch_bounds__(256)
void post_kernel(const float* __restrict__ x, const float* __restrict__ ve,
                 const float* __restrict__ cosb, const float* __restrict__ sinb,
                 const float* __restrict__ Wg, float* __restrict__ qkv)
{
    int wid  = (blockIdx.x * blockDim.x + threadIdx.x) >> 5;
    int lane = threadIdx.x & 31;
    int row = wid / 18;
    int t   = wid - row * 18;
    if (row >= MROWS) return;
    int s = row & (SS - 1);

    if (t < 17) {
        float* vec = qkv + (size_t)row * NQKV + (t < 16 ? t * 64 : 1024);
        float c  = cosb[s * HALF + lane];
        float sn = sinb[s * HALF + lane];
        float x1 = vec[lane];
        float x2 = vec[lane + 32];
        float y1 = x1 * c + x2 * sn;
        float y2 = x2 * c - x1 * sn;
        float ssum = y1 * y1 + y2 * y2;
        #pragma unroll
        for (int off = 16; off; off >>= 1)
            ssum += __shfl_xor_sync(0xffffffffu, ssum, off);
        float sc = rsqrtf(ssum * (1.0f / 64.0f) + EPSF);
        vec[lane]      = y1 * sc;
        vec[lane + 32] = y2 * sc;
    } else {
        float g = x[(size_t)row * EE + lane] * Wg[lane];
        #pragma unroll
        for (int off = 16; off; off >>= 1)
            g += __shfl_xor_sync(0xffffffffu, g, off);
        float gate = 2.0f / (1.0f + __expf(-g));
        float* vvec = qkv + (size_t)row * NQKV + 1088;
        const float* veb = ve + (size_t)row * DD;
        vvec[lane]      += gate * veb[lane];
        vvec[lane + 32] += gate * veb[lane + 32];
    }
}

// ---------------- windowed-causal flash attention, tf32 tensor cores v2 --
// 64q x 64k tiles, 256 threads = 8 warps: (4 m-blocks of 16q) x (2 halves).
// ALL smem tiles in natural row-major [row][d] / [q][key] layout, stride 72:
//  - tile stores: coalesced GMEM float4 + conflict-free STS.128
//    (the previous d-major transpose had 8-way store conflicts: stride 72
//     between consecutive lanes -> 72 mod 32 = 8 -> 4 distinct banks)
//  - fragment gathers: bank = 8*ar + ac + const -> all 32 lanes distinct.
#define TS 72
// smem words: Qs,Ks,Vs,Ps 4*64*72 + hmax/hsum 2*2*64
#define ATT_SMEM ((4 * 64 * TS + 4 * 64) * 4)

__global__ __launch_bounds__(256)
void attn_kernel(const float* __restrict__ qkv, float* __restrict__ out,
                 const int* __restrict__ wptr)
{
    extern __shared__ uint32_t smu[];
    uint32_t* Qs = smu;                  // [64 q][TS]   : Qs[q*TS + d]    (tf32)
    uint32_t* Ks = Qs + 64 * TS;         // [64 key][TS] : Ks[key*TS + d]  (tf32)
    uint32_t* Vs = Ks + 64 * TS;         // [64 key][TS] : Vs[key*TS + d]  (tf32)
    uint32_t* Ps = Vs + 64 * TS;         // [64 q][TS]   : Ps[q*TS + key]  (tf32)
    float* hmax = (float*)(Ps + 64 * TS);   // [2][64]
    float* hsum = hmax + 2 * 64;            // [2][64]

    const int window = *wptr;
    int tid  = threadIdx.x;
    int lane = tid & 31;
    int wid  = tid >> 5;
    int mb   = (wid & 3) * 16;    // warp's q-block base (16 rows)
    int half = wid >> 2;          // 0/1: which 32-col half (keys in QK, d in PV)
    int kb   = half * 32;
    int ar   = lane >> 2;         // 0..7
    int ac   = lane & 3;          // 0..3
    int r0   = mb + ar;           // this thread's q rows within the tile
    int r1   = r0 + 8;

    int qt = (SS / 64 - 1) - blockIdx.x;   // heavy tiles first
    int h  = blockIdx.y;
    int b  = blockIdx.z;
    int q0 = qt * 64;
    const float* base = qkv + (size_t)b * SS * NQKV;

    // load Q tile natural [q][d] (scaled, tf32), float4 path
    #pragma unroll
    for (int it = 0; it < 4; it++) {
        int idx = tid + it * 256;          // 0..1023 float4s
        int qq = idx >> 4;
        int d4 = (idx & 15) << 2;
        float4 v = *(const float4*)&base[(size_t)(q0 + qq) * NQKV + h * 64 + d4];
        *(uint4*)&Qs[qq * TS + d4] =
            make_uint4(f2tf(v.x * 0.125f), f2tf(v.y * 0.125f),
                       f2tf(v.z * 0.125f), f2tf(v.w * 0.125f));
    }

    float of[4][4];
    #pragma unroll
    for (int nb = 0; nb < 4; nb++)
        #pragma unroll
        for (int c = 0; c < 4; c++) of[nb][c] = 0.f;
    float m0r = -INFINITY, m1r = -INFINITY, l0r = 0.f, l1r = 0.f;

    int lo = q0 - window + 1; if (lo < 0) lo = 0;
    int t_lo = lo >> 6;

    for (int t = t_lo; t <= qt; t++) {
        int k0 = t * 64;
        __syncthreads();   // protect tiles/stats from previous iteration
        // load K,V tiles natural [row][d], float4 path
        #pragma unroll
        for (int it = 0; it < 8; it++) {
            int idx = tid + it * 256;      // 0..2047 float4s (K then V)
            int row = (idx >> 4) & 63;
            int d4 = (idx & 15) << 2;
            int off = (idx < 1024) ? 1024 : 1088;
            float4 v = *(const float4*)&base[(size_t)(k0 + row) * NQKV + off + d4];
            uint32_t* dst = (idx < 1024) ? Ks : Vs;
            *(uint4*)&dst[row * TS + d4] =
                make_uint4(f2tf(v.x), f2tf(v.y), f2tf(v.z), f2tf(v.w));
        }
        __syncthreads();

        // ---- S = Q K^T on tensor cores ----
        // A = Q[m=q][k=d] row-major gather; B = K^T[k=d][n=key] gathered from
        // natural Ks[key][d].
        float sf[4][4];
        #pragma unroll
        for (int nb = 0; nb < 4; nb++)
            #pragma unroll
            for (int c = 0; c < 4; c++) sf[nb][c] = 0.f;
        #pragma unroll
        for (int kk = 0; kk < 64; kk += 8) {
            uint32_t afr[4];
            afr[0] = Qs[r0 * TS + kk + ac];
            afr[1] = Qs[r1 * TS + kk + ac];
            afr[2] = Qs[r0 * TS + kk + 4 + ac];
            afr[3] = Qs[r1 * TS + kk + 4 + ac];
            #pragma unroll
            for (int nb = 0; nb < 4; nb++) {
                int key = kb + nb * 8 + ar;
                uint32_t bfr[2];
                bfr[0] = Ks[key * TS + kk + ac];
                bfr[1] = Ks[key * TS + kk + 4 + ac];
                mma_tf32(sf[nb], afr, bfr);
            }
        }

        // ---- mask (boundary tiles only) ----
        bool need_mask = (k0 + 63 > q0) || (q0 + 63 - k0 >= window);
        if (need_mask) {
            int qg0 = q0 + r0, qg1 = q0 + r1;
            #pragma unroll
            for (int nb = 0; nb < 4; nb++) {
                int kg = k0 + kb + nb * 8 + ac * 2;
                #pragma unroll
                for (int cc = 0; cc < 2; cc++) {
                    int kk = kg + cc;
                    int d0 = qg0 - kk, d1 = qg1 - kk;
                    if (d0 < 0 || d0 >= window) sf[nb][cc]     = -INFINITY;
                    if (d1 < 0 || d1 >= window) sf[nb][2 + cc] = -INFINITY;
                }
            }
        }

        // ---- online softmax (fp32, branch-free dead-row handling) ----
        float pm0 = -INFINITY, pm1 = -INFINITY;
        #pragma unroll
        for (int nb = 0; nb < 4; nb++) {
            pm0 = fmaxf(pm0, fmaxf(sf[nb][0], sf[nb][1]));
            pm1 = fmaxf(pm1, fmaxf(sf[nb][2], sf[nb][3]));
        }
        pm0 = fmaxf(pm0, __shfl_xor_sync(0xffffffffu, pm0, 1));
        pm0 = fmaxf(pm0, __shfl_xor_sync(0xffffffffu, pm0, 2));
        pm1 = fmaxf(pm1, __shfl_xor_sync(0xffffffffu, pm1, 1));
        pm1 = fmaxf(pm1, __shfl_xor_sync(0xffffffffu, pm1, 2));
        if (ac == 0) {
            hmax[half * 64 + r0] = pm0;
            hmax[half * 64 + r1] = pm1;
        }
        __syncthreads();
        float mnew0 = fmaxf(m0r, fmaxf(pm0, hmax[(1 - half) * 64 + r0]));
        float mnew1 = fmaxf(m1r, fmaxf(pm1, hmax[(1 - half) * 64 + r1]));
        float ms0 = (mnew0 == -INFINITY) ? 0.f : mnew0;
        float ms1 = (mnew1 == -INFINITY) ? 0.f : mnew1;

        float hs0 = 0.f, hs1 = 0.f;
        #pragma unroll
        for (int nb = 0; nb < 4; nb++) {
            int kcol = kb + nb * 8 + ac * 2;
            float p0 = __expf(sf[nb][0] - ms0);
            float p1 = __expf(sf[nb][1] - ms0);
            float p2 = __expf(sf[nb][2] - ms1);
            float p3 = __expf(sf[nb][3] - ms1);
            hs0 += p0 + p1;
            hs1 += p2 + p3;
            *(uint2*)&Ps[r0 * TS + kcol] = make_uint2(f2tf(p0), f2tf(p1));
            *(uint2*)&Ps[r1 * TS + kcol] = make_uint2(f2tf(p2), f2tf(p3));
        }
        hs0 += __shfl_xor_sync(0xffffffffu, hs0, 1);
        hs0 += __shfl_xor_sync(0xffffffffu, hs0, 2);
        hs1 += __shfl_xor_sync(0xffffffffu, hs1, 1);
        hs1 += __shfl_xor_sync(0xffffffffu, hs1, 2);
        if (ac == 0) {
            hsum[half * 64 + r0] = hs0;
            hsum[half * 64 + r1] = hs1;
        }
        float corr0 = (m0r == -INFINITY) ? 0.f : __expf(m0r - ms0);
        float corr1 = (m1r == -INFINITY) ? 0.f : __expf(m1r - ms1);
        #pragma unroll
        for (int nb = 0; nb < 4; nb++) {
            of[nb][0] *= corr0; of[nb][1] *= corr0;
            of[nb][2] *= corr1; of[nb][3] *= corr1;
        }
        m0r = mnew0; m1r = mnew1;
        __syncthreads();   // Ps + hsum visible to all warps
        l0r = l0r * corr0 + hsum[r0] + hsum[64 + r0];
        l1r = l1r * corr1 + hsum[r1] + hsum[64 + r1];

        // ---- O += P @ V on tensor cores ----
        // A = P[m=q][k=key] row-major gather; B = V[k=key][n=d] natural.
        #pragma unroll
        for (int kk = 0; kk < 64; kk += 8) {
            uint32_t afr[4];
            afr[0] = Ps[r0 * TS + kk + ac];
            afr[1] = Ps[r1 * TS + kk + ac];
            afr[2] = Ps[r0 * TS + kk + 4 + ac];
            afr[3] = Ps[r1 * TS + kk + 4 + ac];
            #pragma unroll
            for (int nb = 0; nb < 4; nb++) {
                uint32_t bfr[2];
                bfr[0] = Vs[(kk + ac) * TS + kb + nb * 8 + ar];
                bfr[1] = Vs[(kk + 4 + ac) * TS + kb + nb * 8 + ar];
                mma_tf32(of[nb], afr, bfr);
            }
        }
    }

    // ---- finalize + write (B,S,H*D) ----
    float inv0 = 1.0f / l0r;
    float inv1 = 1.0f / l1r;
    size_t row0 = (size_t)b * SS + q0 + r0;
    size_t row1 = (size_t)b * SS + q0 + r1;
    #pragma unroll
    for (int nb = 0; nb < 4; nb++) {
        size_t col = h * 64 + kb + nb * 8 + ac * 2;
        *(float2*)&out[row0 * EE + col] =
            make_float2(of[nb][0] * inv0, of[nb][1] * inv0);
        *(float2*)&out[row1 * EE + col] =
            make_float2(of[nb][2] * inv1, of[nb][3] * inv1);
    }
}

// ---------------- launch ----------------
extern "C" void kernel_launch(void* const* d_in, const int* in_sizes, int n_in,
                              void* d_out, int out_size)
{
    const float* x    = (const float*)d_in[0];
    const float* ve   = (const float*)d_in[1];
    const float* cosb = (const float*)d_in[2];
    const float* sinb = (const float*)d_in[3];
    const float* Wq   = (const float*)d_in[4];
    const float* Wk   = (const float*)d_in[5];
    const float* Wv   = (const float*)d_in[6];
    const float* Wo   = (const float*)d_in[7];
    const float* Wg   = (const float*)d_in[8];
    const int*   win  = (const int*)d_in[9];
    float* out = (float*)d_out;

    float *wqkv, *qkv, *attn;
    cudaGetSymbolAddress((void**)&wqkv, g_Wqkv);
    cudaGetSymbolAddress((void**)&qkv,  g_qkv);
    cudaGetSymbolAddress((void**)&attn, g_attn);

    cudaFuncSetAttribute(attn_kernel,
                         cudaFuncAttributeMaxDynamicSharedMemorySize,
                         (int)ATT_SMEM);

    // 1. pack weights
    pack_kernel<<<(1024 * NQKV + 255) / 256, 256>>>(Wq, Wk, Wv, wqkv);

    // 2. fused QKV projection: [4096,1024] @ [1024,1152]  (tf32 tensor core)
    gemm_tf32<<<dim3(NQKV / 128, MROWS / 128), 256>>>(x, wqkv, qkv,
                                                      1024, 1024, NQKV, NQKV);

    // 3. rope + rmsnorm (q,k), gated ve add (v)
    post_kernel<<<(MROWS * 18) / 8, 256>>>(x, ve, cosb, sinb, Wg, qkv);

    // 4. attention (tf32 tensor core)
    attn_kernel<<<dim3(SS / 64, HH, BB), 256, ATT_SMEM>>>(qkv, attn, win);

    // 5. output projection: [4096,1024] @ [1024,1024]  (tf32 tensor core)
    gemm_tf32<<<dim3(EE / 128, MROWS / 128), 256>>>(attn, Wo, out,
                                                    1024, 1024, EE, EE);
}

// round 11
// speedup vs baseline: 2.7670x; 1.0898x over previous
#include <cuda_runtime.h>
#include <cuda_bf16.h>
#include <math.h>
#include <stdint.h>

// Problem constants
#define BB   2
#define SS   2048
#define EE   1024
#define HH   16
#define DD   64
#define HALF 32
#define MROWS 4096            // B*S
#define NQKV  1152            // H*D + D + D
#define EPSF  1.1920929e-07f  // finfo(float32).eps

// ---------------- device scratch (static, allocation-free) ----------------
__device__ float g_Wqkv[1024 * NQKV];   // packed [Wq | Wk | Wv], k-major rows
__device__ float g_qkv[MROWS * NQKV];   // projections, later rope/normed in place
__device__ float g_attn[MROWS * EE];    // attention output (B,S,H*D)

// ---------------- tf32 helpers ----------------
__device__ __forceinline__ uint32_t f2tf(float f) {
    uint32_t u;
    asm("cvt.rna.tf32.f32 %0, %1;" : "=r"(u) : "f"(f));
    return u;
}

__device__ __forceinline__ void mma_tf32(float c[4], const uint32_t a[4],
                                         const uint32_t b[2]) {
    asm volatile(
        "mma.sync.aligned.m16n8k8.row.col.f32.tf32.tf32.f32 "
        "{%0,%1,%2,%3}, {%4,%5,%6,%7}, {%8,%9}, {%0,%1,%2,%3};"
        : "+f"(c[0]), "+f"(c[1]), "+f"(c[2]), "+f"(c[3])
        : "r"(a[0]), "r"(a[1]), "r"(a[2]), "r"(a[3]), "r"(b[0]), "r"(b[1]));
}

// ---------------- pack Wq|Wk|Wv ----------------
__global__ void pack_kernel(const float* __restrict__ Wq,
                            const float* __restrict__ Wk,
                            const float* __restrict__ Wv,
                            float* __restrict__ Wqkv)
{
    int idx = blockIdx.x * blockDim.x + threadIdx.x;
    if (idx >= 1024 * NQKV) return;
    int k = idx / NQKV;
    int n = idx - k * NQKV;
    float v;
    if (n < 1024)       v = Wq[k * 1024 + n];
    else if (n < 1088)  v = Wk[k * 64 + (n - 1024)];
    else                v = Wv[k * 64 + (n - 1088)];
    Wqkv[idx] = v;
}

// ---------------- TF32 tensor-core GEMM (round-5 proven) ----------------
#define GLD 136

__global__ __launch_bounds__(256, 2)
void gemm_tf32(const float* __restrict__ A, const float* __restrict__ B,
               float* __restrict__ C, int K, int lda, int ldb, int ldc)
{
    __shared__ uint32_t As[16][GLD];   // As[k][m] (transposed A tile)
    __shared__ uint32_t Bs[16][GLD];   // Bs[k][n]

    int tid  = threadIdx.x;
    int lane = tid & 31;
    int wid  = tid >> 5;
    int wm   = wid & 3;          // warp m index 0..3 (32 rows each)
    int wn   = wid >> 2;         // warp n index 0..1 (64 cols each)
    size_t m0 = (size_t)blockIdx.y * 128;
    size_t n0 = (size_t)blockIdx.x * 128;

    int arow = tid >> 1;         // 0..127
    int ak   = (tid & 1) * 8;    // 0 or 8
    int brow = tid >> 4;         // 0..15
    int bcol = (tid & 15) * 8;   // 0..120

    const float* Ap = A + (m0 + arow) * (size_t)lda + ak;
    const float* Bp = B + (size_t)brow * ldb + n0 + bcol;

    float4 a0n = *(const float4*)Ap;
    float4 a1n = *(const float4*)(Ap + 4);
    float4 b0n = *(const float4*)Bp;
    float4 b1n = *(const float4*)(Bp + 4);

    float acc[2][8][4];
    #pragma unroll
    for (int mt = 0; mt < 2; mt++)
        #pragma unroll
        for (int nt = 0; nt < 8; nt++)
            #pragma unroll
            for (int r = 0; r < 4; r++) acc[mt][nt][r] = 0.f;

    int ar = lane >> 2;          // 0..7
    int ac = lane & 3;           // 0..3

    for (int k0 = 0; k0 < K; k0 += 16) {
        As[ak + 0][arow] = f2tf(a0n.x);
        As[ak + 1][arow] = f2tf(a0n.y);
        As[ak + 2][arow] = f2tf(a0n.z);
        As[ak + 3][arow] = f2tf(a0n.w);
        As[ak + 4][arow] = f2tf(a1n.x);
        As[ak + 5][arow] = f2tf(a1n.y);
        As[ak + 6][arow] = f2tf(a1n.z);
        As[ak + 7][arow] = f2tf(a1n.w);
        *(uint4*)&Bs[brow][bcol] =
            make_uint4(f2tf(b0n.x), f2tf(b0n.y), f2tf(b0n.z), f2tf(b0n.w));
        *(uint4*)&Bs[brow][bcol + 4] =
            make_uint4(f2tf(b1n.x), f2tf(b1n.y), f2tf(b1n.z), f2tf(b1n.w));
        __syncthreads();

        if (k0 + 16 < K) {
            a0n = *(const float4*)(Ap + k0 + 16);
            a1n = *(const float4*)(Ap + k0 + 20);
            b0n = *(const float4*)(Bp + (size_t)(k0 + 16) * ldb);
            b1n = *(const float4*)(Bp + (size_t)(k0 + 16) * ldb + 4);
        }

        #pragma unroll
        for (int kk = 0; kk < 16; kk += 8) {
            uint32_t afr[2][4];
            #pragma unroll
            for (int mt = 0; mt < 2; mt++) {
                int mb = wm * 32 + mt * 16;
                afr[mt][0] = As[kk + ac][mb + ar];
                afr[mt][1] = As[kk + ac][mb + 8 + ar];
                afr[mt][2] = As[kk + 4 + ac][mb + ar];
                afr[mt][3] = As[kk + 4 + ac][mb + 8 + ar];
            }
            uint32_t bfr[8][2];
            #pragma unroll
            for (int nt = 0; nt < 8; nt++) {
                int nb = wn * 64 + nt * 8;
                bfr[nt][0] = Bs[kk + ac][nb + ar];
                bfr[nt][1] = Bs[kk + 4 + ac][nb + ar];
            }
            #pragma unroll
            for (int mt = 0; mt < 2; mt++)
                #pragma unroll
                for (int nt = 0; nt < 8; nt++)
                    mma_tf32(acc[mt][nt], afr[mt], bfr[nt]);
        }
        __syncthreads();
    }

    #pragma unroll
    for (int mt = 0; mt < 2; mt++) {
        size_t row = m0 + wm * 32 + mt * 16 + ar;
        #pragma unroll
        for (int nt = 0; nt < 8; nt++) {
            size_t col = n0 + wn * 64 + nt * 8 + ac * 2;
            *(float2*)&C[row * (size_t)ldc + col] =
                make_float2(acc[mt][nt][0], acc[mt][nt][1]);
            *(float2*)&C[(row + 8) * (size_t)ldc + col] =
                make_float2(acc[mt][nt][2], acc[mt][nt][3]);
        }
    }
}

// ---------------- RoPE + RMSNorm (q,k) and gated ve add (v), in place -----
__global__ __launch_bounds__(256)
void post_kernel(const float* __restrict__ x, const float* __restrict__ ve,
                 const float* __restrict__ cosb, const float* __restrict__ sinb,
                 const float* __restrict__ Wg, float* __restrict__ qkv)
{
    int wid  = (blockIdx.x * blockDim.x + threadIdx.x) >> 5;
    int lane = threadIdx.x & 31;
    int row = wid / 18;
    int t   = wid - row * 18;
    if (row >= MROWS) return;
    int s = row & (SS - 1);

    if (t < 17) {
        float* vec = qkv + (size_t)row * NQKV + (t < 16 ? t * 64 : 1024);
        float c  = cosb[s * HALF + lane];
        float sn = sinb[s * HALF + lane];
        float x1 = vec[lane];
        float x2 = vec[lane + 32];
        float y1 = x1 * c + x2 * sn;
        float y2 = x2 * c - x1 * sn;
        float ssum = y1 * y1 + y2 * y2;
        #pragma unroll
        for (int off = 16; off; off >>= 1)
            ssum += __shfl_xor_sync(0xffffffffu, ssum, off);
        float sc = rsqrtf(ssum * (1.0f / 64.0f) + EPSF);
        vec[lane]      = y1 * sc;
        vec[lane + 32] = y2 * sc;
    } else {
        float g = x[(size_t)row * EE + lane] * Wg[lane];
        #pragma unroll
        for (int off = 16; off; off >>= 1)
            g += __shfl_xor_sync(0xffffffffu, g, off);
        float gate = 2.0f / (1.0f + __expf(-g));
        float* vvec = qkv + (size_t)row * NQKV + 1088;
        const float* veb = ve + (size_t)row * DD;
        vvec[lane]      += gate * veb[lane];
        vvec[lane + 32] += gate * veb[lane + 32];
    }
}

// ---------------- windowed-causal flash attention, tf32 tensor cores v3 --
// 64q x 64k tiles, 256 threads = 8 warps: (4 m-blocks of 16q) x (2 halves).
// K-PERMUTED smem layouts: within each 8-wide k-group, columns stored as
// [c0,c4,c1,c5,c2,c6,c3,c7], so the mma fragment pair (k=ac, k=ac+4) sits at
// adjacent words 2*ac -> one LDS.64 replaces two LDS.32. Applied to Qs, Ks
// (k = head dim) and Ps (k = key). Vs stays natural (its pairs span rows).
// Arithmetic identical to v2: same values, same mma order.
#define TS 72
// smem words: Qs,Ks,Vs,Ps 4*64*72 + hmax/hsum 2*2*64
#define ATT_SMEM ((4 * 64 * TS + 4 * 64) * 4)

__global__ __launch_bounds__(256)
void attn_kernel(const float* __restrict__ qkv, float* __restrict__ out,
                 const int* __restrict__ wptr)
{
    extern __shared__ uint32_t smu[];
    uint32_t* Qs = smu;                  // [64 q][TS]   k-permuted d cols
    uint32_t* Ks = Qs + 64 * TS;         // [64 key][TS] k-permuted d cols
    uint32_t* Vs = Ks + 64 * TS;         // [64 key][TS] natural
    uint32_t* Ps = Vs + 64 * TS;         // [64 q][TS]   k-permuted key cols
    float* hmax = (float*)(Ps + 64 * TS);   // [2][64]
    float* hsum = hmax + 2 * 64;            // [2][64]

    const int window = *wptr;
    int tid  = threadIdx.x;
    int lane = tid & 31;
    int wid  = tid >> 5;
    int mb   = (wid & 3) * 16;    // warp's q-block base (16 rows)
    int half = wid >> 2;          // 0/1: which 32-col half (keys in QK, d in PV)
    int kb   = half * 32;
    int ar   = lane >> 2;         // 0..7
    int ac   = lane & 3;          // 0..3
    int r0   = mb + ar;           // this thread's q rows within the tile
    int r1   = r0 + 8;

    int qt = (SS / 64 - 1) - blockIdx.x;   // heavy tiles first
    int h  = blockIdx.y;
    int b  = blockIdx.z;
    int q0 = qt * 64;
    const float* base = qkv + (size_t)b * SS * NQKV;

    // Ps store positions for this thread's (col 2ac, col 2ac+1) pair:
    // perm pos(c) = c<4 ? 2c : 2c-7  ->  pos(2ac) and pos(2ac)+2
    int pp0 = (ac < 2) ? 4 * ac : 4 * ac - 7;

    // load Q tile [q][d] k-permuted (scaled, tf32)
    // each uint4 at group g, half hh covers cols {8g+2hh, 8g+2hh+4, 8g+2hh+1, 8g+2hh+5}
    #pragma unroll
    for (int it = 0; it < 4; it++) {
        int idx = tid + it * 256;          // 0..1023 uint4 stores
        int row = idx >> 4;
        int sub = idx & 15;
        int g = sub >> 1, hh = sub & 1;
        const float* src = &base[(size_t)(q0 + row) * NQKV + h * 64 + g * 8 + 2 * hh];
        float2 a = *(const float2*)src;
        float2 c = *(const float2*)(src + 4);
        *(uint4*)&Qs[row * TS + g * 8 + 4 * hh] =
            make_uint4(f2tf(a.x * 0.125f), f2tf(c.x * 0.125f),
                       f2tf(a.y * 0.125f), f2tf(c.y * 0.125f));
    }

    float of[4][4];
    #pragma unroll
    for (int nb = 0; nb < 4; nb++)
        #pragma unroll
        for (int c = 0; c < 4; c++) of[nb][c] = 0.f;
    float m0r = -INFINITY, m1r = -INFINITY, l0r = 0.f, l1r = 0.f;

    int lo = q0 - window + 1; if (lo < 0) lo = 0;
    int t_lo = lo >> 6;

    for (int t = t_lo; t <= qt; t++) {
        int k0 = t * 64;
        __syncthreads();   // protect tiles/stats from previous iteration
        // K tile: k-permuted (same scheme as Q)
        #pragma unroll
        for (int it = 0; it < 4; it++) {
            int idx = tid + it * 256;
            int row = idx >> 4;
            int sub = idx & 15;
            int g = sub >> 1, hh = sub & 1;
            const float* src = &base[(size_t)(k0 + row) * NQKV + 1024 + g * 8 + 2 * hh];
            float2 a = *(const float2*)src;
            float2 c = *(const float2*)(src + 4);
            *(uint4*)&Ks[row * TS + g * 8 + 4 * hh] =
                make_uint4(f2tf(a.x), f2tf(c.x), f2tf(a.y), f2tf(c.y));
        }
        // V tile: natural layout, float4 path
        #pragma unroll
        for (int it = 0; it < 4; it++) {
            int idx = tid + it * 256;
            int row = idx >> 4;
            int d4 = (idx & 15) << 2;
            float4 v = *(const float4*)&base[(size_t)(k0 + row) * NQKV + 1088 + d4];
            *(uint4*)&Vs[row * TS + d4] =
                make_uint4(f2tf(v.x), f2tf(v.y), f2tf(v.z), f2tf(v.w));
        }
        __syncthreads();

        // ---- S = Q K^T on tensor cores (LDS.64 fragment loads) ----
        float sf[4][4];
        #pragma unroll
        for (int nb = 0; nb < 4; nb++)
            #pragma unroll
            for (int c = 0; c < 4; c++) sf[nb][c] = 0.f;
        #pragma unroll
        for (int kk = 0; kk < 64; kk += 8) {
            uint2 qa = *(const uint2*)&Qs[r0 * TS + kk + 2 * ac];
            uint2 qb = *(const uint2*)&Qs[r1 * TS + kk + 2 * ac];
            uint32_t afr[4] = {qa.x, qb.x, qa.y, qb.y};
            #pragma unroll
            for (int nb = 0; nb < 4; nb++) {
                int key = kb + nb * 8 + ar;
                uint2 kv = *(const uint2*)&Ks[key * TS + kk + 2 * ac];
                uint32_t bfr[2] = {kv.x, kv.y};
                mma_tf32(sf[nb], afr, bfr);
            }
        }

        // ---- mask (boundary tiles only) ----
        bool need_mask = (k0 + 63 > q0) || (q0 + 63 - k0 >= window);
        if (need_mask) {
            int qg0 = q0 + r0, qg1 = q0 + r1;
            #pragma unroll
            for (int nb = 0; nb < 4; nb++) {
                int kg = k0 + kb + nb * 8 + ac * 2;
                #pragma unroll
                for (int cc = 0; cc < 2; cc++) {
                    int kk = kg + cc;
                    int d0 = qg0 - kk, d1 = qg1 - kk;
                    if (d0 < 0 || d0 >= window) sf[nb][cc]     = -INFINITY;
                    if (d1 < 0 || d1 >= window) sf[nb][2 + cc] = -INFINITY;
                }
            }
        }

        // ---- online softmax (fp32, branch-free dead-row handling) ----
        float pm0 = -INFINITY, pm1 = -INFINITY;
        #pragma unroll
        for (int nb = 0; nb < 4; nb++) {
            pm0 = fmaxf(pm0, fmaxf(sf[nb][0], sf[nb][1]));
            pm1 = fmaxf(pm1, fmaxf(sf[nb][2], sf[nb][3]));
        }
        pm0 = fmaxf(pm0, __shfl_xor_sync(0xffffffffu, pm0, 1));
        pm0 = fmaxf(pm0, __shfl_xor_sync(0xffffffffu, pm0, 2));
        pm1 = fmaxf(pm1, __shfl_xor_sync(0xffffffffu, pm1, 1));
        pm1 = fmaxf(pm1, __shfl_xor_sync(0xffffffffu, pm1, 2));
        if (ac == 0) {
            hmax[half * 64 + r0] = pm0;
            hmax[half * 64 + r1] = pm1;
        }
        __syncthreads();
        float mnew0 = fmaxf(m0r, fmaxf(pm0, hmax[(1 - half) * 64 + r0]));
        float mnew1 = fmaxf(m1r, fmaxf(pm1, hmax[(1 - half) * 64 + r1]));
        float ms0 = (mnew0 == -INFINITY) ? 0.f : mnew0;
        float ms1 = (mnew1 == -INFINITY) ? 0.f : mnew1;

        float hs0 = 0.f, hs1 = 0.f;
        #pragma unroll
        for (int nb = 0; nb < 4; nb++) {
            int gbase = kb + nb * 8;        // key group base (multiple of 8)
            float p0 = __expf(sf[nb][0] - ms0);
            float p1 = __expf(sf[nb][1] - ms0);
            float p2 = __expf(sf[nb][2] - ms1);
            float p3 = __expf(sf[nb][3] - ms1);
            hs0 += p0 + p1;
            hs1 += p2 + p3;
            // permuted positions: col 2ac -> pp0, col 2ac+1 -> pp0+2
            Ps[r0 * TS + gbase + pp0]     = f2tf(p0);
            Ps[r0 * TS + gbase + pp0 + 2] = f2tf(p1);
            Ps[r1 * TS + gbase + pp0]     = f2tf(p2);
            Ps[r1 * TS + gbase + pp0 + 2] = f2tf(p3);
        }
        hs0 += __shfl_xor_sync(0xffffffffu, hs0, 1);
        hs0 += __shfl_xor_sync(0xffffffffu, hs0, 2);
        hs1 += __shfl_xor_sync(0xffffffffu, hs1, 1);
        hs1 += __shfl_xor_sync(0xffffffffu, hs1, 2);
        if (ac == 0) {
            hsum[half * 64 + r0] = hs0;
            hsum[half * 64 + r1] = hs1;
        }
        float corr0 = (m0r == -INFINITY) ? 0.f : __expf(m0r - ms0);
        float corr1 = (m1r == -INFINITY) ? 0.f : __expf(m1r - ms1);
        #pragma unroll
        for (int nb = 0; nb < 4; nb++) {
            of[nb][0] *= corr0; of[nb][1] *= corr0;
            of[nb][2] *= corr1; of[nb][3] *= corr1;
        }
        m0r = mnew0; m1r = mnew1;
        __syncthreads();   // Ps + hsum visible to all warps
        l0r = l0r * corr0 + hsum[r0] + hsum[64 + r0];
        l1r = l1r * corr1 + hsum[r1] + hsum[64 + r1];

        // ---- O += P @ V on tensor cores ----
        // A from k-permuted Ps (LDS.64); B from natural Vs (rows differ -> scalar)
        #pragma unroll
        for (int kk = 0; kk < 64; kk += 8) {
            uint2 pa = *(const uint2*)&Ps[r0 * TS + kk + 2 * ac];
            uint2 pb = *(const uint2*)&Ps[r1 * TS + kk + 2 * ac];
            uint32_t afr[4] = {pa.x, pb.x, pa.y, pb.y};
            #pragma unroll
            for (int nb = 0; nb < 4; nb++) {
                uint32_t bfr[2];
                bfr[0] = Vs[(kk + ac) * TS + kb + nb * 8 + ar];
                bfr[1] = Vs[(kk + 4 + ac) * TS + kb + nb * 8 + ar];
                mma_tf32(of[nb], afr, bfr);
            }
        }
    }

    // ---- finalize + write (B,S,H*D) ----
    float inv0 = 1.0f / l0r;
    float inv1 = 1.0f / l1r;
    size_t row0 = (size_t)b * SS + q0 + r0;
    size_t row1 = (size_t)b * SS + q0 + r1;
    #pragma unroll
    for (int nb = 0; nb < 4; nb++) {
        size_t col = h * 64 + kb + nb * 8 + ac * 2;
        *(float2*)&out[row0 * EE + col] =
            make_float2(of[nb][0] * inv0, of[nb][1] * inv0);
        *(float2*)&out[row1 * EE + col] =
            make_float2(of[nb][2] * inv1, of[nb][3] * inv1);
    }
}

// ---------------- launch ----------------
extern "C" void kernel_launch(void* const* d_in, const int* in_sizes, int n_in,
                              void* d_out, int out_size)
{
    const float* x    = (const float*)d_in[0];
    const float* ve   = (const float*)d_in[1];
    const float* cosb = (const float*)d_in[2];
    const float* sinb = (const float*)d_in[3];
    const float* Wq   = (const float*)d_in[4];
    const float* Wk   = (const float*)d_in[5];
    const float* Wv   = (const float*)d_in[6];
    const float* Wo   = (const float*)d_in[7];
    const float* Wg   = (const float*)d_in[8];
    const int*   win  = (const int*)d_in[9];
    float* out = (float*)d_out;

    float *wqkv, *qkv, *attn;
    cudaGetSymbolAddress((void**)&wqkv, g_Wqkv);
    cudaGetSymbolAddress((void**)&qkv,  g_qkv);
    cudaGetSymbolAddress((void**)&attn, g_attn);

    cudaFuncSetAttribute(attn_kernel,
                         cudaFuncAttributeMaxDynamicSharedMemorySize,
                         (int)ATT_SMEM);

    // 1. pack weights
    pack_kernel<<<(1024 * NQKV + 255) / 256, 256>>>(Wq, Wk, Wv, wqkv);

    // 2. fused QKV projection: [4096,1024] @ [1024,1152]  (tf32 tensor core)
    gemm_tf32<<<dim3(NQKV / 128, MROWS / 128), 256>>>(x, wqkv, qkv,
                                                      1024, 1024, NQKV, NQKV);

    // 3. rope + rmsnorm (q,k), gated ve add (v)
    post_kernel<<<(MROWS * 18) / 8, 256>>>(x, ve, cosb, sinb, Wg, qkv);

    // 4. attention (tf32 tensor core)
    attn_kernel<<<dim3(SS / 64, HH, BB), 256, ATT_SMEM>>>(qkv, attn, win);

    // 5. output projection: [4096,1024] @ [1024,1024]  (tf32 tensor core)
    gemm_tf32<<<dim3(EE / 128, MROWS / 128), 256>>>(attn, Wo, out,
                                                    1024, 1024, EE, EE);
}

// round 12
// speedup vs baseline: 2.9447x; 1.0642x over previous
#include <cuda_runtime.h>
#include <cuda_bf16.h>
#include <math.h>
#include <stdint.h>

// Problem constants
#define BB   2
#define SS   2048
#define EE   1024
#define HH   16
#define DD   64
#define HALF 32
#define MROWS 4096            // B*S
#define NQKV  1152            // H*D + D + D
#define EPSF  1.1920929e-07f  // finfo(float32).eps

// ---------------- device scratch (static, allocation-free) ----------------
__device__ float g_Wqkv[1024 * NQKV];   // packed [Wq | Wk | Wv], k-major rows
__device__ float g_qkv[MROWS * NQKV];   // projections, later rope/normed in place
__device__ float g_attn[MROWS * EE];    // attention output (B,S,H*D)

// ---------------- tf32 helpers ----------------
__device__ __forceinline__ uint32_t f2tf(float f) {
    uint32_t u;
    asm("cvt.rna.tf32.f32 %0, %1;" : "=r"(u) : "f"(f));
    return u;
}

__device__ __forceinline__ void mma_tf32(float c[4], const uint32_t a[4],
                                         const uint32_t b[2]) {
    asm volatile(
        "mma.sync.aligned.m16n8k8.row.col.f32.tf32.tf32.f32 "
        "{%0,%1,%2,%3}, {%4,%5,%6,%7}, {%8,%9}, {%0,%1,%2,%3};"
        : "+f"(c[0]), "+f"(c[1]), "+f"(c[2]), "+f"(c[3])
        : "r"(a[0]), "r"(a[1]), "r"(a[2]), "r"(a[3]), "r"(b[0]), "r"(b[1]));
}

// ---------------- pack Wq|Wk|Wv ----------------
__global__ void pack_kernel(const float* __restrict__ Wq,
                            const float* __restrict__ Wk,
                            const float* __restrict__ Wv,
                            float* __restrict__ Wqkv)
{
    int idx = blockIdx.x * blockDim.x + threadIdx.x;
    if (idx >= 1024 * NQKV) return;
    int k = idx / NQKV;
    int n = idx - k * NQKV;
    float v;
    if (n < 1024)       v = Wq[k * 1024 + n];
    else if (n < 1088)  v = Wk[k * 64 + (n - 1024)];
    else                v = Wv[k * 64 + (n - 1088)];
    Wqkv[idx] = v;
}

// ---------------- TF32 tensor-core GEMM (round-5 proven) ----------------
#define GLD 136

__global__ __launch_bounds__(256, 2)
void gemm_tf32(const float* __restrict__ A, const float* __restrict__ B,
               float* __restrict__ C, int K, int lda, int ldb, int ldc)
{
    __shared__ uint32_t As[16][GLD];   // As[k][m] (transposed A tile)
    __shared__ uint32_t Bs[16][GLD];   // Bs[k][n]

    int tid  = threadIdx.x;
    int lane = tid & 31;
    int wid  = tid >> 5;
    int wm   = wid & 3;          // warp m index 0..3 (32 rows each)
    int wn   = wid >> 2;         // warp n index 0..1 (64 cols each)
    size_t m0 = (size_t)blockIdx.y * 128;
    size_t n0 = (size_t)blockIdx.x * 128;

    int arow = tid >> 1;         // 0..127
    int ak   = (tid & 1) * 8;    // 0 or 8
    int brow = tid >> 4;         // 0..15
    int bcol = (tid & 15) * 8;   // 0..120

    const float* Ap = A + (m0 + arow) * (size_t)lda + ak;
    const float* Bp = B + (size_t)brow * ldb + n0 + bcol;

    float4 a0n = *(const float4*)Ap;
    float4 a1n = *(const float4*)(Ap + 4);
    float4 b0n = *(const float4*)Bp;
    float4 b1n = *(const float4*)(Bp + 4);

    float acc[2][8][4];
    #pragma unroll
    for (int mt = 0; mt < 2; mt++)
        #pragma unroll
        for (int nt = 0; nt < 8; nt++)
            #pragma unroll
            for (int r = 0; r < 4; r++) acc[mt][nt][r] = 0.f;

    int ar = lane >> 2;          // 0..7
    int ac = lane & 3;           // 0..3

    for (int k0 = 0; k0 < K; k0 += 16) {
        As[ak + 0][arow] = f2tf(a0n.x);
        As[ak + 1][arow] = f2tf(a0n.y);
        As[ak + 2][arow] = f2tf(a0n.z);
        As[ak + 3][arow] = f2tf(a0n.w);
        As[ak + 4][arow] = f2tf(a1n.x);
        As[ak + 5][arow] = f2tf(a1n.y);
        As[ak + 6][arow] = f2tf(a1n.z);
        As[ak + 7][arow] = f2tf(a1n.w);
        *(uint4*)&Bs[brow][bcol] =
            make_uint4(f2tf(b0n.x), f2tf(b0n.y), f2tf(b0n.z), f2tf(b0n.w));
        *(uint4*)&Bs[brow][bcol + 4] =
            make_uint4(f2tf(b1n.x), f2tf(b1n.y), f2tf(b1n.z), f2tf(b1n.w));
        __syncthreads();

        if (k0 + 16 < K) {
            a0n = *(const float4*)(Ap + k0 + 16);
            a1n = *(const float4*)(Ap + k0 + 20);
            b0n = *(const float4*)(Bp + (size_t)(k0 + 16) * ldb);
            b1n = *(const float4*)(Bp + (size_t)(k0 + 16) * ldb + 4);
        }

        #pragma unroll
        for (int kk = 0; kk < 16; kk += 8) {
            uint32_t afr[2][4];
            #pragma unroll
            for (int mt = 0; mt < 2; mt++) {
                int mb = wm * 32 + mt * 16;
                afr[mt][0] = As[kk + ac][mb + ar];
                afr[mt][1] = As[kk + ac][mb + 8 + ar];
                afr[mt][2] = As[kk + 4 + ac][mb + ar];
                afr[mt][3] = As[kk + 4 + ac][mb + 8 + ar];
            }
            uint32_t bfr[8][2];
            #pragma unroll
            for (int nt = 0; nt < 8; nt++) {
                int nb = wn * 64 + nt * 8;
                bfr[nt][0] = Bs[kk + ac][nb + ar];
                bfr[nt][1] = Bs[kk + 4 + ac][nb + ar];
            }
            #pragma unroll
            for (int mt = 0; mt < 2; mt++)
                #pragma unroll
                for (int nt = 0; nt < 8; nt++)
                    mma_tf32(acc[mt][nt], afr[mt], bfr[nt]);
        }
        __syncthreads();
    }

    #pragma unroll
    for (int mt = 0; mt < 2; mt++) {
        size_t row = m0 + wm * 32 + mt * 16 + ar;
        #pragma unroll
        for (int nt = 0; nt < 8; nt++) {
            size_t col = n0 + wn * 64 + nt * 8 + ac * 2;
            *(float2*)&C[row * (size_t)ldc + col] =
                make_float2(acc[mt][nt][0], acc[mt][nt][1]);
            *(float2*)&C[(row + 8) * (size_t)ldc + col] =
                make_float2(acc[mt][nt][2], acc[mt][nt][3]);
        }
    }
}

// ---------------- RoPE + RMSNorm (q,k) and gated ve add (v), in place -----
__global__ __launch_bounds__(256)
void post_kernel(const float* __restrict__ x, const float* __restrict__ ve,
                 const float* __restrict__ cosb, const float* __restrict__ sinb,
                 const float* __restrict__ Wg, float* __restrict__ qkv)
{
    int wid  = (blockIdx.x * blockDim.x + threadIdx.x) >> 5;
    int lane = threadIdx.x & 31;
    int row = wid / 18;
    int t   = wid - row * 18;
    if (row >= MROWS) return;
    int s = row & (SS - 1);

    if (t < 17) {
        float* vec = qkv + (size_t)row * NQKV + (t < 16 ? t * 64 : 1024);
        float c  = cosb[s * HALF + lane];
        float sn = sinb[s * HALF + lane];
        float x1 = vec[lane];
        float x2 = vec[lane + 32];
        float y1 = x1 * c + x2 * sn;
        float y2 = x2 * c - x1 * sn;
        float ssum = y1 * y1 + y2 * y2;
        #pragma unroll
        for (int off = 16; off; off >>= 1)
            ssum += __shfl_xor_sync(0xffffffffu, ssum, off);
        float sc = rsqrtf(ssum * (1.0f / 64.0f) + EPSF);
        vec[lane]      = y1 * sc;
        vec[lane + 32] = y2 * sc;
    } else {
        float g = x[(size_t)row * EE + lane] * Wg[lane];
        #pragma unroll
        for (int off = 16; off; off >>= 1)
            g += __shfl_xor_sync(0xffffffffu, g, off);
        float gate = 2.0f / (1.0f + __expf(-g));
        float* vvec = qkv + (size_t)row * NQKV + 1088;
        const float* veb = ve + (size_t)row * DD;
        vvec[lane]      += gate * veb[lane];
        vvec[lane + 32] += gate * veb[lane + 32];
    }
}

// ---------------- windowed-causal flash attention, tf32 tensor cores v4 --
// WARP-AUTONOMOUS: 64q x 64k tiles, 128 threads = 4 warps; each warp owns
// 16 q-rows x ALL 64 keys. Softmax is fully warp-local (4-lane shfl reduce,
// no cross-warp hmax/hsum exchange); Ps rows are warp-private (__syncwarp
// instead of __syncthreads). 2 block syncs per k-tile instead of 4.
// K-permuted layouts from v3 retained (LDS.64 fragment loads; arithmetic
// identical -> rel_err must stay bit-identical).
#define TS 72
// smem words: Qs,Ks,Vs,Ps 4*64*72
#define ATT_SMEM ((4 * 64 * TS) * 4)

__global__ __launch_bounds__(128)
void attn_kernel(const float* __restrict__ qkv, float* __restrict__ out,
                 const int* __restrict__ wptr)
{
    extern __shared__ uint32_t smu[];
    uint32_t* Qs = smu;                  // [64 q][TS]   k-permuted d cols
    uint32_t* Ks = Qs + 64 * TS;         // [64 key][TS] k-permuted d cols
    uint32_t* Vs = Ks + 64 * TS;         // [64 key][TS] natural
    uint32_t* Ps = Vs + 64 * TS;         // [64 q][TS]   k-permuted key cols

    const int window = *wptr;
    int tid  = threadIdx.x;
    int lane = tid & 31;
    int wid  = tid >> 5;          // 0..3
    int mb   = wid * 16;          // warp's q-block base (16 rows)
    int ar   = lane >> 2;         // 0..7
    int ac   = lane & 3;          // 0..3
    int r0   = mb + ar;           // this thread's q rows within the tile
    int r1   = r0 + 8;

    int qt = (SS / 64 - 1) - blockIdx.x;   // heavy tiles first
    int h  = blockIdx.y;
    int b  = blockIdx.z;
    int q0 = qt * 64;
    const float* base = qkv + (size_t)b * SS * NQKV;

    // Ps store positions for this thread's (col 2ac, col 2ac+1) pair:
    // perm pos(c) = c<4 ? 2c : 2c-7  ->  pos(2ac) and pos(2ac)+2
    int pp0 = (ac < 2) ? 4 * ac : 4 * ac - 7;

    // load Q tile [q][d] k-permuted (scaled, tf32)
    #pragma unroll
    for (int it = 0; it < 8; it++) {
        int idx = tid + it * 128;          // 0..1023 uint4 stores
        int row = idx >> 4;
        int sub = idx & 15;
        int g = sub >> 1, hh = sub & 1;
        const float* src = &base[(size_t)(q0 + row) * NQKV + h * 64 + g * 8 + 2 * hh];
        float2 a = *(const float2*)src;
        float2 c = *(const float2*)(src + 4);
        *(uint4*)&Qs[row * TS + g * 8 + 4 * hh] =
            make_uint4(f2tf(a.x * 0.125f), f2tf(c.x * 0.125f),
                       f2tf(a.y * 0.125f), f2tf(c.y * 0.125f));
    }

    float of[8][4];
    #pragma unroll
    for (int nb = 0; nb < 8; nb++)
        #pragma unroll
        for (int c = 0; c < 4; c++) of[nb][c] = 0.f;
    float m0r = -INFINITY, m1r = -INFINITY, l0r = 0.f, l1r = 0.f;

    int lo = q0 - window + 1; if (lo < 0) lo = 0;
    int t_lo = lo >> 6;

    for (int t = t_lo; t <= qt; t++) {
        int k0 = t * 64;
        __syncthreads();   // protect Ks/Vs from previous-iteration readers
        // K tile: k-permuted (same scheme as Q)
        #pragma unroll
        for (int it = 0; it < 8; it++) {
            int idx = tid + it * 128;
            int row = idx >> 4;
            int sub = idx & 15;
            int g = sub >> 1, hh = sub & 1;
            const float* src = &base[(size_t)(k0 + row) * NQKV + 1024 + g * 8 + 2 * hh];
            float2 a = *(const float2*)src;
            float2 c = *(const float2*)(src + 4);
            *(uint4*)&Ks[row * TS + g * 8 + 4 * hh] =
                make_uint4(f2tf(a.x), f2tf(c.x), f2tf(a.y), f2tf(c.y));
        }
        // V tile: natural layout, float4 path
        #pragma unroll
        for (int it = 0; it < 8; it++) {
            int idx = tid + it * 128;
            int row = idx >> 4;
            int d4 = (idx & 15) << 2;
            float4 v = *(const float4*)&base[(size_t)(k0 + row) * NQKV + 1088 + d4];
            *(uint4*)&Vs[row * TS + d4] =
                make_uint4(f2tf(v.x), f2tf(v.y), f2tf(v.z), f2tf(v.w));
        }
        __syncthreads();

        // ---- S = Q K^T on tensor cores (warp-local 16q x 64k) ----
        float sf[8][4];
        #pragma unroll
        for (int nb = 0; nb < 8; nb++)
            #pragma unroll
            for (int c = 0; c < 4; c++) sf[nb][c] = 0.f;
        #pragma unroll
        for (int kk = 0; kk < 64; kk += 8) {
            uint2 qa = *(const uint2*)&Qs[r0 * TS + kk + 2 * ac];
            uint2 qb = *(const uint2*)&Qs[r1 * TS + kk + 2 * ac];
            uint32_t afr[4] = {qa.x, qb.x, qa.y, qb.y};
            #pragma unroll
            for (int nb = 0; nb < 8; nb++) {
                int key = nb * 8 + ar;
                uint2 kv = *(const uint2*)&Ks[key * TS + kk + 2 * ac];
                uint32_t bfr[2] = {kv.x, kv.y};
                mma_tf32(sf[nb], afr, bfr);
            }
        }

        // ---- mask (boundary tiles only) ----
        bool need_mask = (k0 + 63 > q0) || (q0 + 63 - k0 >= window);
        if (need_mask) {
            int qg0 = q0 + r0, qg1 = q0 + r1;
            #pragma unroll
            for (int nb = 0; nb < 8; nb++) {
                int kg = k0 + nb * 8 + ac * 2;
                #pragma unroll
                for (int cc = 0; cc < 2; cc++) {
                    int kk = kg + cc;
                    int d0 = qg0 - kk, d1 = qg1 - kk;
                    if (d0 < 0 || d0 >= window) sf[nb][cc]     = -INFINITY;
                    if (d1 < 0 || d1 >= window) sf[nb][2 + cc] = -INFINITY;
                }
            }
        }

        // ---- online softmax (fp32, warp-local, branch-free dead rows) ----
        float pm0 = -INFINITY, pm1 = -INFINITY;
        #pragma unroll
        for (int nb = 0; nb < 8; nb++) {
            pm0 = fmaxf(pm0, fmaxf(sf[nb][0], sf[nb][1]));
            pm1 = fmaxf(pm1, fmaxf(sf[nb][2], sf[nb][3]));
        }
        pm0 = fmaxf(pm0, __shfl_xor_sync(0xffffffffu, pm0, 1));
        pm0 = fmaxf(pm0, __shfl_xor_sync(0xffffffffu, pm0, 2));
        pm1 = fmaxf(pm1, __shfl_xor_sync(0xffffffffu, pm1, 1));
        pm1 = fmaxf(pm1, __shfl_xor_sync(0xffffffffu, pm1, 2));
        float mnew0 = fmaxf(m0r, pm0);
        float mnew1 = fmaxf(m1r, pm1);
        float ms0 = (mnew0 == -INFINITY) ? 0.f : mnew0;
        float ms1 = (mnew1 == -INFINITY) ? 0.f : mnew1;

        float hs0 = 0.f, hs1 = 0.f;
        #pragma unroll
        for (int nb = 0; nb < 8; nb++) {
            int gbase = nb * 8;             // key group base
            float p0 = __expf(sf[nb][0] - ms0);
            float p1 = __expf(sf[nb][1] - ms0);
            float p2 = __expf(sf[nb][2] - ms1);
            float p3 = __expf(sf[nb][3] - ms1);
            hs0 += p0 + p1;
            hs1 += p2 + p3;
            // permuted positions: col 2ac -> pp0, col 2ac+1 -> pp0+2
            Ps[r0 * TS + gbase + pp0]     = f2tf(p0);
            Ps[r0 * TS + gbase + pp0 + 2] = f2tf(p1);
            Ps[r1 * TS + gbase + pp0]     = f2tf(p2);
            Ps[r1 * TS + gbase + pp0 + 2] = f2tf(p3);
        }
        hs0 += __shfl_xor_sync(0xffffffffu, hs0, 1);
        hs0 += __shfl_xor_sync(0xffffffffu, hs0, 2);
        hs1 += __shfl_xor_sync(0xffffffffu, hs1, 1);
        hs1 += __shfl_xor_sync(0xffffffffu, hs1, 2);
        float corr0 = (m0r == -INFINITY) ? 0.f : __expf(m0r - ms0);
        float corr1 = (m1r == -INFINITY) ? 0.f : __expf(m1r - ms1);
        #pragma unroll
        for (int nb = 0; nb < 8; nb++) {
            of[nb][0] *= corr0; of[nb][1] *= corr0;
            of[nb][2] *= corr1; of[nb][3] *= corr1;
        }
        m0r = mnew0; m1r = mnew1;
        l0r = l0r * corr0 + hs0;
        l1r = l1r * corr1 + hs1;
        __syncwarp();   // Ps rows are warp-private: warp-level visibility only

        // ---- O += P @ V on tensor cores (warp-local 16q x 64d) ----
        #pragma unroll
        for (int kk = 0; kk < 64; kk += 8) {
            uint2 pa = *(const uint2*)&Ps[r0 * TS + kk + 2 * ac];
            uint2 pb = *(const uint2*)&Ps[r1 * TS + kk + 2 * ac];
            uint32_t afr[4] = {pa.x, pb.x, pa.y, pb.y};
            #pragma unroll
            for (int nb = 0; nb < 8; nb++) {
                uint32_t bfr[2];
                bfr[0] = Vs[(kk + ac) * TS + nb * 8 + ar];
                bfr[1] = Vs[(kk + 4 + ac) * TS + nb * 8 + ar];
                mma_tf32(of[nb], afr, bfr);
            }
        }
    }

    // ---- finalize + write (B,S,H*D) ----
    float inv0 = 1.0f / l0r;
    float inv1 = 1.0f / l1r;
    size_t row0 = (size_t)b * SS + q0 + r0;
    size_t row1 = (size_t)b * SS + q0 + r1;
    #pragma unroll
    for (int nb = 0; nb < 8; nb++) {
        size_t col = h * 64 + nb * 8 + ac * 2;
        *(float2*)&out[row0 * EE + col] =
            make_float2(of[nb][0] * inv0, of[nb][1] * inv0);
        *(float2*)&out[row1 * EE + col] =
            make_float2(of[nb][2] * inv1, of[nb][3] * inv1);
    }
}

// ---------------- launch ----------------
extern "C" void kernel_launch(void* const* d_in, const int* in_sizes, int n_in,
                              void* d_out, int out_size)
{
    const float* x    = (const float*)d_in[0];
    const float* ve   = (const float*)d_in[1];
    const float* cosb = (const float*)d_in[2];
    const float* sinb = (const float*)d_in[3];
    const float* Wq   = (const float*)d_in[4];
    const float* Wk   = (const float*)d_in[5];
    const float* Wv   = (const float*)d_in[6];
    const float* Wo   = (const float*)d_in[7];
    const float* Wg   = (const float*)d_in[8];
    const int*   win  = (const int*)d_in[9];
    float* out = (float*)d_out;

    float *wqkv, *qkv, *attn;
    cudaGetSymbolAddress((void**)&wqkv, g_Wqkv);
    cudaGetSymbolAddress((void**)&qkv,  g_qkv);
    cudaGetSymbolAddress((void**)&attn, g_attn);

    cudaFuncSetAttribute(attn_kernel,
                         cudaFuncAttributeMaxDynamicSharedMemorySize,
                         (int)ATT_SMEM);

    // 1. pack weights
    pack_kernel<<<(1024 * NQKV + 255) / 256, 256>>>(Wq, Wk, Wv, wqkv);

    // 2. fused QKV projection: [4096,1024] @ [1024,1152]  (tf32 tensor core)
    gemm_tf32<<<dim3(NQKV / 128, MROWS / 128), 256>>>(x, wqkv, qkv,
                                                      1024, 1024, NQKV, NQKV);

    // 3. rope + rmsnorm (q,k), gated ve add (v)
    post_kernel<<<(MROWS * 18) / 8, 256>>>(x, ve, cosb, sinb, Wg, qkv);

    // 4. attention (tf32 tensor core, warp-autonomous)
    attn_kernel<<<dim3(SS / 64, HH, BB), 128, ATT_SMEM>>>(qkv, attn, win);

    // 5. output projection: [4096,1024] @ [1024,1024]  (tf32 tensor core)
    gemm_tf32<<<dim3(EE / 128, MROWS / 128), 256>>>(attn, Wo, out,
                                                    1024, 1024, EE, EE);
}